// round 10
// baseline (speedup 1.0000x reference)
#include <cuda_runtime.h>
#include <cstdint>

// ---------------------------------------------------------------------------
// KAN 2-layer fused, round 10: R9 tile config (128x128, best) at 512 threads
// (16 warps, 4/SMSP) to cover LDS/HMMA latency. Producers re-split:
// A = slot+half (R8 scheme), B = 1 slot/thread.
//   D[o,b] = sum_{i,g} W[o,i,g] * f_g(x[b,i])
//   f = {basis_0..7(x), silu(x)},  W = {ssp*coef_0..7, sb}
//   Chunk K layout: kk = g*8 + ii  (9 planes of 8 inputs, K=72/chunk)
//   K2 CTA: M=128 (o) x N=128 (b) x K=432; grid (2 o-tiles x 64 splits).
// ---------------------------------------------------------------------------

#define B_     128
#define IN_    3072
#define H_     256
#define OUT_   10
#define KSPLIT 64
#define IPC    48          // inputs per CTA
#define NCH    6           // chunks of 8 inputs
#define NKS    9           // feature planes per chunk
#define NTH    512

__device__ float g_Y1p[KSPLIT * B_ * H_];    // layer-1 partials [split][b][o]
__device__ float g_Y1[B_ * H_];              // reduced layer-1 pre-activation

// ---- smem: A/B tiles 36KB each, double buffered = 144KB (1 CTA/SM) --------
#define SM_A0    0
#define SM_A1    36864
#define SM_B0    73728
#define SM_B1    110592
#define SMEM_TOTAL 147456
#define SP       132       // writeout transpose pitch

// ---- helpers ---------------------------------------------------------------
__device__ __forceinline__ void mma8(float d[4], const uint32_t a[4], const uint32_t b[2]) {
    asm volatile("mma.sync.aligned.m16n8k8.row.col.f32.tf32.tf32.f32 "
        "{%0,%1,%2,%3}, {%4,%5,%6,%7}, {%8,%9}, {%0,%1,%2,%3};"
        : "+f"(d[0]), "+f"(d[1]), "+f"(d[2]), "+f"(d[3])
        : "r"(a[0]), "r"(a[1]), "r"(a[2]), "r"(a[3]), "r"(b[0]), "r"(b[1]));
}
__device__ __forceinline__ float silu_f(float x) { return x / (1.0f + __expf(-x)); }
__device__ __forceinline__ float selu_f(float x) {
    const float scale = 1.0507009873554805f;
    const float alpha = 1.6732632423543772f;
    return x > 0.0f ? scale * x : scale * alpha * expm1f(x);
}

// Closed-form cubic B-spline on uniform extended grid t_j = -2.2 + 0.4 j
// (validated rounds 4-9 vs Cox-de-Boor).
struct Bsp { float w0, w1, w2, w3; int m; };
__device__ __forceinline__ Bsp bspline4(float x) {
    Bsp r;
    float tpos = (x + 2.2f) * 2.5f;
    float mf = floorf(tpos);
    r.m = (int)mf;
    float u = tpos - mf;
    float u2 = u * u, u3 = u2 * u, om = 1.0f - u;
    bool valid = (x >= -2.2f) && (r.m <= 10);
    float s = valid ? (1.0f / 6.0f) : 0.0f;
    r.w0 = om * om * om * s;
    r.w1 = (3.0f * u3 - 6.0f * u2 + 4.0f) * s;
    r.w2 = (-3.0f * u3 + 3.0f * u2 + 3.0f * u + 1.0f) * s;
    r.w3 = u3 * s;
    return r;
}
__device__ __forceinline__ float bsp_at(const Bsp& r, int g) {
    int d = r.m - g;
    float v = 0.0f;
    v = (d == 3) ? r.w0 : v;
    v = (d == 2) ? r.w1 : v;
    v = (d == 1) ? r.w2 : v;
    v = (d == 0) ? r.w3 : v;
    return v;
}

// ---------------------------------------------------------------------------
// K2: layer-1 GEMM on mma.sync, 512 threads.
//   A_s[g][mt8][lane32]{float4}: plane stride 1024 u32. Fragment slot
//     (mt,lane): lane = r8*4+ic; word j=q*2+h -> edge (o=mt*16+r8+8h, i=ic+4q)
//   B_s[g][nt16][lane32]{float2}: plane stride 1024 u32. Slot (nt,lane):
//     lane = (b&7)*4+ic; words: ii = ic (w0), ic+4 (w1); b = nt*8 + (lane>>2)
// Warp grid 4m x 4n; warp tile 32o x 32b (mi 0..1, ni 0..3).
// ---------------------------------------------------------------------------
__global__ void __launch_bounds__(NTH, 1) k2_mma(const float* __restrict__ x,
                                                const float* __restrict__ coef1,
                                                const float* __restrict__ sb1,
                                                const float* __restrict__ ssp1) {
    extern __shared__ __align__(16) char smem[];

    const int tid  = threadIdx.x;
    const int lane = tid & 31;
    const int wid  = tid >> 5;
    const int wm   = wid >> 2;          // 0..3 : 32 o per warp-row
    const int wn   = wid & 3;           // 0..3 : 32 b per warp-col
    const int o0   = blockIdx.x * 128;
    const int split = blockIdx.y;
    const int i0   = split * IPC;

    float acc[2][4][4];
#pragma unroll
    for (int mi = 0; mi < 2; mi++)
#pragma unroll
        for (int ni = 0; ni < 4; ni++)
#pragma unroll
            for (int w = 0; w < 4; w++) acc[mi][ni][w] = 0.0f;

    // ---- A: slot = tid>>1 (256 slots), half = tid&1 ----
    //   half 0: c0 -> planes 0-3, plus sb -> plane 8
    //   half 1: c1 -> planes 4-7
    const int a_slot = tid >> 1;
    const int a_half = tid & 1;
    const int a_mt   = a_slot >> 5;
    const int a_ln   = a_slot & 31;
    const int a_r8   = a_ln >> 2;
    const int a_ic   = a_ln & 3;
    const uint32_t a_base = (uint32_t)(a_mt * 32 + a_ln) * 4;   // u32; +g*1024

    // ---- B: one slot per thread (512 slots) ----
    const int b_nt  = tid >> 5;
    const int b_ln  = tid & 31;
    const int b_row = b_nt * 8 + (b_ln >> 2);
    const int b_ic  = b_ln & 3;
    const uint32_t b_base = (uint32_t)(b_nt * 32 + b_ln) * 2;   // u32; +g*1024

    // ---- staging registers ----
    float4 pc[4];                 // c0 (half 0) or c1 (half 1) for 4 edges
    float  psp[4], psb[4];
    float  px0, px1;

    auto ldgA = [&](int ib) {
#pragma unroll
        for (int q = 0; q < 2; q++)
#pragma unroll
            for (int h = 0; h < 2; h++) {
                int j = q * 2 + h;                        // fragment word
                int o = o0 + a_mt * 16 + a_r8 + 8 * h;
                int i = ib + a_ic + 4 * q;
                int e = o * IN_ + i;
                pc[j]  = ((const float4*)coef1)[e * 2 + a_half];
                psp[j] = ssp1[e];
                if (a_half == 0) psb[j] = sb1[e];
            }
    };
    auto ldgB = [&](int ib) {
        px0 = x[b_row * IN_ + ib + b_ic];
        px1 = x[b_row * IN_ + ib + b_ic + 4];
    };
    auto stsA = [&](uint32_t offA) {
        float* As = (float*)(smem + offA);
        const int g0 = a_half * 4;       // planes 0-3 or 4-7
        *(float4*)&As[(g0 + 0) * 1024 + a_base] =
            make_float4(psp[0]*pc[0].x, psp[1]*pc[1].x, psp[2]*pc[2].x, psp[3]*pc[3].x);
        *(float4*)&As[(g0 + 1) * 1024 + a_base] =
            make_float4(psp[0]*pc[0].y, psp[1]*pc[1].y, psp[2]*pc[2].y, psp[3]*pc[3].y);
        *(float4*)&As[(g0 + 2) * 1024 + a_base] =
            make_float4(psp[0]*pc[0].z, psp[1]*pc[1].z, psp[2]*pc[2].z, psp[3]*pc[3].z);
        *(float4*)&As[(g0 + 3) * 1024 + a_base] =
            make_float4(psp[0]*pc[0].w, psp[1]*pc[1].w, psp[2]*pc[2].w, psp[3]*pc[3].w);
        if (a_half == 0)
            *(float4*)&As[8 * 1024 + a_base] = make_float4(psb[0], psb[1], psb[2], psb[3]);
    };
    auto prodB = [&](uint32_t offB) {
        uint32_t* Bs = (uint32_t*)(smem + offB);
        uint32_t* base = Bs + b_base;
#pragma unroll
        for (int g = 0; g < 8; g++)
            *(float2*)&base[g * 1024] = make_float2(0.0f, 0.0f);
        Bsp bs0 = bspline4(px0);
        Bsp bs1 = bspline4(px1);
        float w0[4] = { bs0.w0, bs0.w1, bs0.w2, bs0.w3 };
        float w1[4] = { bs1.w0, bs1.w1, bs1.w2, bs1.w3 };
#pragma unroll
        for (int j = 0; j < 4; j++) {
            int g0 = bs0.m - 3 + j;
            if (g0 >= 0 && g0 <= 7) base[g0 * 1024]     = __float_as_uint(w0[j]);
            int g1 = bs1.m - 3 + j;
            if (g1 >= 0 && g1 <= 7) base[g1 * 1024 + 1] = __float_as_uint(w1[j]);
        }
        *(float2*)&base[8 * 1024] = make_float2(silu_f(px0), silu_f(px1));
    };
    auto consume = [&](uint32_t offA, uint32_t offB) {
        const float4* As = (const float4*)(smem + offA);
        const float2* Bs = (const float2*)(smem + offB);
#pragma unroll
        for (int ks = 0; ks < NKS; ks++) {
            uint32_t af[2][4], bf[4][2];
#pragma unroll
            for (int mi = 0; mi < 2; mi++) {
                float4 v = As[(ks * 8 + wm * 2 + mi) * 32 + lane];
                af[mi][0] = __float_as_uint(v.x); af[mi][1] = __float_as_uint(v.y);
                af[mi][2] = __float_as_uint(v.z); af[mi][3] = __float_as_uint(v.w);
            }
#pragma unroll
            for (int ni = 0; ni < 4; ni++) {
                float2 v = Bs[(ks * 16 + wn * 4 + ni) * 32 + lane];
                bf[ni][0] = __float_as_uint(v.x); bf[ni][1] = __float_as_uint(v.y);
            }
#pragma unroll
            for (int mi = 0; mi < 2; mi++)
#pragma unroll
                for (int ni = 0; ni < 4; ni++) mma8(acc[mi][ni], af[mi], bf[ni]);
        }
    };

    // --- pipeline: ldg(t+1); consume(t); sts(t+1); sync ---
    ldgA(i0); ldgB(i0);
    stsA(SM_A0); prodB(SM_B0);
    __syncthreads();

    for (int t = 0; t < NCH; t++) {
        const uint32_t offA = (t & 1) ? SM_A1 : SM_A0;
        const uint32_t offB = (t & 1) ? SM_B1 : SM_B0;
        const uint32_t nfA  = (t & 1) ? SM_A0 : SM_A1;
        const uint32_t nfB  = (t & 1) ? SM_B0 : SM_B1;
        if (t + 1 < NCH) { ldgA(i0 + (t + 1) * 8); ldgB(i0 + (t + 1) * 8); }
        consume(offA, offB);
        if (t + 1 < NCH) { stsA(nfA); prodB(nfB); }
        __syncthreads();
    }

    // --- writeout: transpose through smem, coalesced float4 partial stores ---
    {
        float* S = (float*)(smem + SM_A0);          // [128 b][pitch SP]
        const int r = lane >> 2, c = lane & 3;
#pragma unroll
        for (int mi = 0; mi < 2; mi++)
#pragma unroll
            for (int ni = 0; ni < 4; ni++)
#pragma unroll
                for (int w = 0; w < 4; w++) {
                    int o_l = (wm * 2 + mi) * 16 + r + 8 * (w >> 1);
                    int b_l = (wn * 4 + ni) * 8 + 2 * c + (w & 1);
                    S[b_l * SP + o_l] = acc[mi][ni][w];
                }
        __syncthreads();
        float* Y = g_Y1p + split * (B_ * H_);
#pragma unroll
        for (int p = 0; p < 8; p++) {
            int idx = tid + NTH * p;
            int bb = idx >> 5, o4 = idx & 31;
            float4 v = *(float4*)&S[bb * SP + o4 * 4];
            *(float4*)&Y[bb * H_ + o0 + o4 * 4] = v;
        }
    }
}

// ---------------------------------------------------------------------------
// K3a: split reduction, 256 CTAs (validated round 5).
// ---------------------------------------------------------------------------
__global__ void __launch_bounds__(256) k3a_reduce() {
    __shared__ float4 sred[8][32];
    const int t = threadIdx.x, c = blockIdx.x;
    const int lane = t & 31, w = t >> 5;
    const int out = c * 32 + lane;
    const int b = out >> 6, o4 = out & 63;

    const float4* P = (const float4*)g_Y1p;
    float4 acc = make_float4(0.f, 0.f, 0.f, 0.f);
#pragma unroll
    for (int k = 0; k < 8; k++) {
        int s = w * 8 + k;
        float4 v = P[(s * B_ + b) * (H_ / 4) + o4];
        acc.x += v.x; acc.y += v.y; acc.z += v.z; acc.w += v.w;
    }
    sred[w][lane] = acc;
    __syncthreads();
    if (t < 32) {
        float4 a = sred[0][t];
#pragma unroll
        for (int j = 1; j < 8; j++) {
            float4 v = sred[j][t];
            a.x += v.x; a.y += v.y; a.z += v.z; a.w += v.w;
        }
        ((float4*)g_Y1)[c * 32 + t] = a;
    }
}

// ---------------------------------------------------------------------------
// K3b: layer 2, shfl reduction (validated round 5).
// ---------------------------------------------------------------------------
__global__ void __launch_bounds__(256) k3b_layer2(const float* __restrict__ coef2,
                                                 const float* __restrict__ sb2,
                                                 const float* __restrict__ ssp2,
                                                 float* __restrict__ out) {
    const int b = blockIdx.x;
    const int t = threadIdx.x;
    const int lane = t & 31, w = t >> 5;

    float h = selu_f(g_Y1[b * H_ + t]);
    Bsp bs = bspline4(h);
    float f0 = silu_f(h);
    float fb[8];
#pragma unroll
    for (int g = 0; g < 8; g++) fb[g] = bsp_at(bs, g);

    __shared__ float red[OUT_ * 8];
    float val[OUT_];
#pragma unroll
    for (int o = 0; o < OUT_; o++) {
        int e = o * H_ + t;
        float4 c0 = ((const float4*)coef2)[e * 2];
        float4 c1 = ((const float4*)coef2)[e * 2 + 1];
        float sp = ssp2[e];
        float spline = fb[0] * c0.x + fb[1] * c0.y + fb[2] * c0.z + fb[3] * c0.w
                     + fb[4] * c1.x + fb[5] * c1.y + fb[6] * c1.z + fb[7] * c1.w;
        val[o] = sb2[e] * f0 + sp * spline;
    }
#pragma unroll
    for (int o = 0; o < OUT_; o++) {
#pragma unroll
        for (int off = 16; off > 0; off >>= 1)
            val[o] += __shfl_down_sync(0xFFFFFFFFu, val[o], off);
    }
    if (lane == 0) {
#pragma unroll
        for (int o = 0; o < OUT_; o++) red[o * 8 + w] = val[o];
    }
    __syncthreads();
    if (t < OUT_) {
        float s = 0.0f;
#pragma unroll
        for (int j = 0; j < 8; j++) s += red[t * 8 + j];
        out[b * OUT_ + t] = s;
    }
}

// ---------------------------------------------------------------------------
extern "C" void kernel_launch(void* const* d_in, const int* in_sizes, int n_in,
                              void* d_out, int out_size) {
    const float* x     = (const float*)d_in[0];
    const float* coef1 = (const float*)d_in[1];
    const float* sb1   = (const float*)d_in[2];
    const float* ssp1  = (const float*)d_in[3];
    const float* coef2 = (const float*)d_in[4];
    const float* sb2   = (const float*)d_in[5];
    const float* ssp2  = (const float*)d_in[6];
    float* out = (float*)d_out;

    cudaFuncSetAttribute(k2_mma, cudaFuncAttributeMaxDynamicSharedMemorySize, SMEM_TOTAL);
    k2_mma<<<dim3(2, KSPLIT), NTH, SMEM_TOTAL>>>(x, coef1, sb1, ssp1);
    k3a_reduce<<<(B_ * H_) / (32 * 4), 256>>>();
    k3b_layer2<<<B_, 256>>>(coef2, sb2, ssp2, out);
}

// round 11
// speedup vs baseline: 1.0996x; 1.0996x over previous
#include <cuda_runtime.h>
#include <cuda_fp16.h>
#include <cstdint>

// ---------------------------------------------------------------------------
// KAN 2-layer fused, round 11: fp16 m16n8k16 MMA (same 10-bit mantissa as
// tf32, half the smem traffic + half the HMMA count). R9 structure: 128x128
// tile, 8 warps (2m x 4n), chunk = 8 inputs.
//   Chunk K = 72: 4 x K16 steps (basis plane pairs) + 1 x K8 silu step.
//   D[o,b] = sum_{i,g} W[o,i,g] * f_g(x[b,i])
// ---------------------------------------------------------------------------

#define B_     128
#define IN_    3072
#define H_     256
#define OUT_   10
#define KSPLIT 64
#define IPC    48
#define NCH    6

__device__ float g_Y1p[KSPLIT * B_ * H_];
__device__ float g_Y1[B_ * H_];

// ---- smem: A/B tiles 18KB each, double buffered = 72KB --------------------
#define SM_A0    0
#define SM_A1    18432
#define SM_B0    36864
#define SM_B1    55296
#define SMEM_TOTAL 73728
#define SP       132

// ---- helpers ---------------------------------------------------------------
__device__ __forceinline__ uint32_t packh2(float lo, float hi) {
    __half2 h = __floats2half2_rn(lo, hi);
    return *(uint32_t*)&h;
}
__device__ __forceinline__ uint16_t h16(float v) {
    __half h = __float2half_rn(v);
    return __half_as_ushort(h);
}
__device__ __forceinline__ void mma16(float d[4], const uint4& a, const uint2& b) {
    asm volatile("mma.sync.aligned.m16n8k16.row.col.f32.f16.f16.f32 "
        "{%0,%1,%2,%3}, {%4,%5,%6,%7}, {%8,%9}, {%0,%1,%2,%3};"
        : "+f"(d[0]), "+f"(d[1]), "+f"(d[2]), "+f"(d[3])
        : "r"(a.x), "r"(a.y), "r"(a.z), "r"(a.w), "r"(b.x), "r"(b.y));
}
__device__ __forceinline__ void mma8h(float d[4], const uint2& a, uint32_t b) {
    asm volatile("mma.sync.aligned.m16n8k8.row.col.f32.f16.f16.f32 "
        "{%0,%1,%2,%3}, {%4,%5}, {%6}, {%0,%1,%2,%3};"
        : "+f"(d[0]), "+f"(d[1]), "+f"(d[2]), "+f"(d[3])
        : "r"(a.x), "r"(a.y), "r"(b));
}
__device__ __forceinline__ float silu_f(float x) { return x / (1.0f + __expf(-x)); }
__device__ __forceinline__ float selu_f(float x) {
    const float scale = 1.0507009873554805f;
    const float alpha = 1.6732632423543772f;
    return x > 0.0f ? scale * x : scale * alpha * expm1f(x);
}

// Closed-form cubic B-spline (validated rounds 4-10 vs Cox-de-Boor).
struct Bsp { float w0, w1, w2, w3; int m; };
__device__ __forceinline__ Bsp bspline4(float x) {
    Bsp r;
    float tpos = (x + 2.2f) * 2.5f;
    float mf = floorf(tpos);
    r.m = (int)mf;
    float u = tpos - mf;
    float u2 = u * u, u3 = u2 * u, om = 1.0f - u;
    bool valid = (x >= -2.2f) && (r.m <= 10);
    float s = valid ? (1.0f / 6.0f) : 0.0f;
    r.w0 = om * om * om * s;
    r.w1 = (3.0f * u3 - 6.0f * u2 + 4.0f) * s;
    r.w2 = (-3.0f * u3 + 3.0f * u2 + 3.0f * u + 1.0f) * s;
    r.w3 = u3 * s;
    return r;
}
__device__ __forceinline__ float bsp_at(const Bsp& r, int g) {
    int d = r.m - g;
    float v = 0.0f;
    v = (d == 3) ? r.w0 : v;
    v = (d == 2) ? r.w1 : v;
    v = (d == 1) ? r.w2 : v;
    v = (d == 0) ? r.w3 : v;
    return v;
}

// float4 component by compile-time index
#define F4C(v, k) ((k)==0 ? (v).x : (k)==1 ? (v).y : (k)==2 ? (v).z : (v).w)

// ---------------------------------------------------------------------------
// K2: layer-1 GEMM on fp16 mma.sync.
// A buffer: 4 K16 steps @ j*4096 (slot 16B = [h2(r,i0|i1)g0, h2(r+8)g0,
//   h2(r)g1, h2(r+8)g1]) + silu step @16384 (slot 8B). Total 18KB.
// B buffer: 4 K16 steps @ j*4096 (slot 8B = [h2(w_g0(x0),w_g0(x1)),
//   h2(w_g1..)]) + silu @16384 (slot 4B). Total 18KB.
// ---------------------------------------------------------------------------
__global__ void __launch_bounds__(256, 1) k2_mma(const float* __restrict__ x,
                                                const float* __restrict__ coef1,
                                                const float* __restrict__ sb1,
                                                const float* __restrict__ ssp1) {
    extern __shared__ __align__(16) char smem[];

    const int tid  = threadIdx.x;
    const int lane = tid & 31;
    const int wid  = tid >> 5;
    const int wm   = wid >> 2;          // 0..1 : 64 o per warp
    const int wn   = wid & 3;           // 0..3 : 32 b per warp
    const int o0   = blockIdx.x * 128;
    const int split = blockIdx.y;
    const int ibase0 = split * IPC;

    float acc[4][4][4];
#pragma unroll
    for (int mi = 0; mi < 4; mi++)
#pragma unroll
        for (int ni = 0; ni < 4; ni++)
#pragma unroll
            for (int w = 0; w < 4; w++) acc[mi][ni][w] = 0.0f;

    // ---- A slot: one per thread (8 mt x 32 ln) ----
    const int a_mt = tid >> 5, a_ln = tid & 31;
    const int a_r  = a_ln >> 2, a_c = a_ln & 3;
    const uint32_t a_slotb = (uint32_t)(a_mt * 32 + a_ln) * 16;
    const int a_orow = o0 + a_mt * 16 + a_r;          // and +8

    // ---- B units: two per thread ----
    int b_row[2], b_c[2];
    uint32_t b_slotb[2];
#pragma unroll
    for (int p = 0; p < 2; p++) {
        int s = tid + 256 * p;
        int nt = s >> 5, ln = s & 31;
        b_row[p]  = nt * 8 + (ln >> 2);
        b_c[p]    = ln & 3;
        b_slotb[p] = (uint32_t)(nt * 32 + ln) * 8;
    }

    // ---- staging ----
    float4 t0[4], t1[4];
    float  psp[4], psb[4];
    float  px[2][2];

    auto ldgA = [&](int ib) {
#pragma unroll
        for (int e = 0; e < 4; e++) {
            int o = a_orow + 8 * (e >> 1);
            int i = ib + 2 * a_c + (e & 1);
            int idx = o * IN_ + i;
            t0[e]  = ((const float4*)coef1)[idx * 2];
            t1[e]  = ((const float4*)coef1)[idx * 2 + 1];
            psp[e] = ssp1[idx];
            psb[e] = sb1[idx];
        }
    };
    auto ldgB = [&](int ib) {
#pragma unroll
        for (int p = 0; p < 2; p++) {
            px[p][0] = x[b_row[p] * IN_ + ib + 2 * b_c[p]];
            px[p][1] = x[b_row[p] * IN_ + ib + 2 * b_c[p] + 1];
        }
    };
    auto stsA = [&](uint32_t offA) {
        char* As = smem + offA;
#pragma unroll
        for (int j = 0; j < 4; j++) {
            const int g0 = 2 * j, g1 = 2 * j + 1;
            float v00, v01, v10, v11, q00, q01, q10, q11;
            if (g0 < 4) { v00 = F4C(t0[0], g0); v01 = F4C(t0[1], g0);
                          v10 = F4C(t0[2], g0); v11 = F4C(t0[3], g0); }
            else        { v00 = F4C(t1[0], g0 - 4); v01 = F4C(t1[1], g0 - 4);
                          v10 = F4C(t1[2], g0 - 4); v11 = F4C(t1[3], g0 - 4); }
            if (g1 < 4) { q00 = F4C(t0[0], g1); q01 = F4C(t0[1], g1);
                          q10 = F4C(t0[2], g1); q11 = F4C(t0[3], g1); }
            else        { q00 = F4C(t1[0], g1 - 4); q01 = F4C(t1[1], g1 - 4);
                          q10 = F4C(t1[2], g1 - 4); q11 = F4C(t1[3], g1 - 4); }
            uint4 u;
            u.x = packh2(psp[0] * v00, psp[1] * v01);
            u.y = packh2(psp[2] * v10, psp[3] * v11);
            u.z = packh2(psp[0] * q00, psp[1] * q01);
            u.w = packh2(psp[2] * q10, psp[3] * q11);
            *(uint4*)(As + j * 4096 + a_slotb) = u;
        }
        uint2 v;
        v.x = packh2(psb[0], psb[1]);
        v.y = packh2(psb[2], psb[3]);
        *(uint2*)(As + 16384 + (a_slotb >> 1)) = v;   // slot*8
    };
    auto prodB = [&](uint32_t offB) {
        char* Bb = smem + offB;
#pragma unroll
        for (int p = 0; p < 2; p++) {
            const uint32_t sb8 = b_slotb[p];
#pragma unroll
            for (int j = 0; j < 4; j++)
                *(uint2*)(Bb + j * 4096 + sb8) = make_uint2(0u, 0u);
            Bsp q0 = bspline4(px[p][0]);
            Bsp q1 = bspline4(px[p][1]);
            float wa[4] = { q0.w0, q0.w1, q0.w2, q0.w3 };
            float wb[4] = { q1.w0, q1.w1, q1.w2, q1.w3 };
#pragma unroll
            for (int k = 0; k < 4; k++) {
                int ga = q0.m - 3 + k;
                if (ga >= 0 && ga <= 7)
                    *(uint16_t*)(Bb + (ga >> 1) * 4096 + sb8 + (ga & 1) * 4)     = h16(wa[k]);
                int gb = q1.m - 3 + k;
                if (gb >= 0 && gb <= 7)
                    *(uint16_t*)(Bb + (gb >> 1) * 4096 + sb8 + (gb & 1) * 4 + 2) = h16(wb[k]);
            }
            *(uint32_t*)(Bb + 16384 + (sb8 >> 1)) =
                packh2(silu_f(px[p][0]), silu_f(px[p][1]));
        }
    };
    auto consume = [&](uint32_t offA, uint32_t offB) {
        const char* As = smem + offA;
        const char* Bb = smem + offB;
#pragma unroll
        for (int j = 0; j < 4; j++) {
            uint4 af[4];
            uint2 bf[4];
#pragma unroll
            for (int mi = 0; mi < 4; mi++)
                af[mi] = *(const uint4*)(As + j * 4096 + (((wm * 4 + mi) * 32 + lane) << 4));
#pragma unroll
            for (int ni = 0; ni < 4; ni++)
                bf[ni] = *(const uint2*)(Bb + j * 4096 + (((wn * 4 + ni) * 32 + lane) << 3));
#pragma unroll
            for (int mi = 0; mi < 4; mi++)
#pragma unroll
                for (int ni = 0; ni < 4; ni++) mma16(acc[mi][ni], af[mi], bf[ni]);
        }
        // silu K8 step
        uint2 af2[4];
        uint32_t bf2[4];
#pragma unroll
        for (int mi = 0; mi < 4; mi++)
            af2[mi] = *(const uint2*)(As + 16384 + (((wm * 4 + mi) * 32 + lane) << 3));
#pragma unroll
        for (int ni = 0; ni < 4; ni++)
            bf2[ni] = *(const uint32_t*)(Bb + 16384 + (((wn * 4 + ni) * 32 + lane) << 2));
#pragma unroll
        for (int mi = 0; mi < 4; mi++)
#pragma unroll
            for (int ni = 0; ni < 4; ni++) mma8h(acc[mi][ni], af2[mi], bf2[ni]);
    };

    // --- pipeline: ldg(t+1); consume(t); sts(t+1); sync ---
    ldgA(ibase0); ldgB(ibase0);
    stsA(SM_A0); prodB(SM_B0);
    __syncthreads();

    for (int t = 0; t < NCH; t++) {
        const uint32_t offA = (t & 1) ? SM_A1 : SM_A0;
        const uint32_t offB = (t & 1) ? SM_B1 : SM_B0;
        const uint32_t nfA  = (t & 1) ? SM_A0 : SM_A1;
        const uint32_t nfB  = (t & 1) ? SM_B0 : SM_B1;
        if (t + 1 < NCH) { ldgA(ibase0 + (t + 1) * 8); ldgB(ibase0 + (t + 1) * 8); }
        consume(offA, offB);
        if (t + 1 < NCH) { stsA(nfA); prodB(nfB); }
        __syncthreads();
    }

    // --- writeout (R9-validated): transpose via smem, float4 stores ---
    {
        float* S = (float*)smem;                    // [128 b][pitch SP]
        const int r = lane >> 2, c = lane & 3;
#pragma unroll
        for (int mi = 0; mi < 4; mi++)
#pragma unroll
            for (int ni = 0; ni < 4; ni++)
#pragma unroll
                for (int w = 0; w < 4; w++) {
                    int o_l = (wm * 4 + mi) * 16 + r + 8 * (w >> 1);
                    int b_l = (wn * 4 + ni) * 8 + 2 * c + (w & 1);
                    S[b_l * SP + o_l] = acc[mi][ni][w];
                }
        __syncthreads();
        float* Y = g_Y1p + split * (B_ * H_);
#pragma unroll
        for (int p = 0; p < 16; p++) {
            int idx = tid + 256 * p;
            int bb = idx >> 5, o4 = idx & 31;
            float4 v = *(float4*)&S[bb * SP + o4 * 4];
            *(float4*)&Y[bb * H_ + o0 + o4 * 4] = v;
        }
    }
}

// ---------------------------------------------------------------------------
// K3a: split reduction, 256 CTAs (validated round 5).
// ---------------------------------------------------------------------------
__global__ void __launch_bounds__(256) k3a_reduce() {
    __shared__ float4 sred[8][32];
    const int t = threadIdx.x, c = blockIdx.x;
    const int lane = t & 31, w = t >> 5;
    const int out = c * 32 + lane;
    const int b = out >> 6, o4 = out & 63;

    const float4* P = (const float4*)g_Y1p;
    float4 acc = make_float4(0.f, 0.f, 0.f, 0.f);
#pragma unroll
    for (int k = 0; k < 8; k++) {
        int s = w * 8 + k;
        float4 v = P[(s * B_ + b) * (H_ / 4) + o4];
        acc.x += v.x; acc.y += v.y; acc.z += v.z; acc.w += v.w;
    }
    sred[w][lane] = acc;
    __syncthreads();
    if (t < 32) {
        float4 a = sred[0][t];
#pragma unroll
        for (int j = 1; j < 8; j++) {
            float4 v = sred[j][t];
            a.x += v.x; a.y += v.y; a.z += v.z; a.w += v.w;
        }
        ((float4*)g_Y1)[c * 32 + t] = a;
    }
}

// ---------------------------------------------------------------------------
// K3b: layer 2, shfl reduction (validated round 5).
// ---------------------------------------------------------------------------
__global__ void __launch_bounds__(256) k3b_layer2(const float* __restrict__ coef2,
                                                 const float* __restrict__ sb2,
                                                 const float* __restrict__ ssp2,
                                                 float* __restrict__ out) {
    const int b = blockIdx.x;
    const int t = threadIdx.x;
    const int lane = t & 31, w = t >> 5;

    float h = selu_f(g_Y1[b * H_ + t]);
    Bsp bs = bspline4(h);
    float f0 = silu_f(h);
    float fb[8];
#pragma unroll
    for (int g = 0; g < 8; g++) fb[g] = bsp_at(bs, g);

    __shared__ float red[OUT_ * 8];
    float val[OUT_];
#pragma unroll
    for (int o = 0; o < OUT_; o++) {
        int e = o * H_ + t;
        float4 c0 = ((const float4*)coef2)[e * 2];
        float4 c1 = ((const float4*)coef2)[e * 2 + 1];
        float sp = ssp2[e];
        float spline = fb[0] * c0.x + fb[1] * c0.y + fb[2] * c0.z + fb[3] * c0.w
                     + fb[4] * c1.x + fb[5] * c1.y + fb[6] * c1.z + fb[7] * c1.w;
        val[o] = sb2[e] * f0 + sp * spline;
    }
#pragma unroll
    for (int o = 0; o < OUT_; o++) {
#pragma unroll
        for (int off = 16; off > 0; off >>= 1)
            val[o] += __shfl_down_sync(0xFFFFFFFFu, val[o], off);
    }
    if (lane == 0) {
#pragma unroll
        for (int o = 0; o < OUT_; o++) red[o * 8 + w] = val[o];
    }
    __syncthreads();
    if (t < OUT_) {
        float s = 0.0f;
#pragma unroll
        for (int j = 0; j < 8; j++) s += red[t * 8 + j];
        out[b * OUT_ + t] = s;
    }
}

// ---------------------------------------------------------------------------
extern "C" void kernel_launch(void* const* d_in, const int* in_sizes, int n_in,
                              void* d_out, int out_size) {
    const float* x     = (const float*)d_in[0];
    const float* coef1 = (const float*)d_in[1];
    const float* sb1   = (const float*)d_in[2];
    const float* ssp1  = (const float*)d_in[3];
    const float* coef2 = (const float*)d_in[4];
    const float* sb2   = (const float*)d_in[5];
    const float* ssp2  = (const float*)d_in[6];
    float* out = (float*)d_out;

    cudaFuncSetAttribute(k2_mma, cudaFuncAttributeMaxDynamicSharedMemorySize, SMEM_TOTAL);
    k2_mma<<<dim3(2, KSPLIT), 256, SMEM_TOTAL>>>(x, coef1, sb1, ssp1);
    k3a_reduce<<<(B_ * H_) / (32 * 4), 256>>>();
    k3b_layer2<<<B_, 256>>>(coef2, sb2, ssp2, out);
}

// round 12
// speedup vs baseline: 1.1881x; 1.0804x over previous
#include <cuda_runtime.h>
#include <cuda_fp16.h>
#include <cstdint>

// ---------------------------------------------------------------------------
// KAN 2-layer fused, round 12: warp-specialized K2.
//   512 threads: warps 0-7 consume (fp16 m16n8k16 MMA, R11-validated),
//   warps 8-15 produce (LDG -> pack fp16 fragments -> STS, R11-validated).
//   3-stage ring (36KB/stage), per-stage rendezvous named barrier
//   (bar.sync id 1+s, 512 by BOTH roles): produce(t+1) || consume(t).
//   Chunk = 8 inputs: 4 x K16 basis steps + 1 x K8 silu step (K=72).
//   K2 CTA: M=128 (o) x N=128 (b) x K=432; grid (2 o-tiles x 64 splits).
// ---------------------------------------------------------------------------

#define B_     128
#define IN_    3072
#define H_     256
#define OUT_   10
#define KSPLIT 64
#define IPC    48
#define NCH    6
#define STGB   36864        // stage bytes: 18KB A + 18KB B
#define SMEM_TOTAL (3 * STGB)
#define SP     132

__device__ float g_Y1p[KSPLIT * B_ * H_];
__device__ float g_Y1[B_ * H_];

// ---- helpers ---------------------------------------------------------------
__device__ __forceinline__ uint32_t packh2(float lo, float hi) {
    __half2 h = __floats2half2_rn(lo, hi);
    return *(uint32_t*)&h;
}
__device__ __forceinline__ uint16_t h16(float v) {
    __half h = __float2half_rn(v);
    return __half_as_ushort(h);
}
__device__ __forceinline__ void mma16(float d[4], const uint4& a, const uint2& b) {
    asm volatile("mma.sync.aligned.m16n8k16.row.col.f32.f16.f16.f32 "
        "{%0,%1,%2,%3}, {%4,%5,%6,%7}, {%8,%9}, {%0,%1,%2,%3};"
        : "+f"(d[0]), "+f"(d[1]), "+f"(d[2]), "+f"(d[3])
        : "r"(a.x), "r"(a.y), "r"(a.z), "r"(a.w), "r"(b.x), "r"(b.y));
}
__device__ __forceinline__ void mma8h(float d[4], const uint2& a, uint32_t b) {
    asm volatile("mma.sync.aligned.m16n8k8.row.col.f32.f16.f16.f32 "
        "{%0,%1,%2,%3}, {%4,%5}, {%6}, {%0,%1,%2,%3};"
        : "+f"(d[0]), "+f"(d[1]), "+f"(d[2]), "+f"(d[3])
        : "r"(a.x), "r"(a.y), "r"(b));
}
#define BARS(id, cnt) asm volatile("bar.sync %0, %1;" :: "r"(id), "r"(cnt) : "memory")

__device__ __forceinline__ float silu_f(float x) { return x / (1.0f + __expf(-x)); }
__device__ __forceinline__ float selu_f(float x) {
    const float scale = 1.0507009873554805f;
    const float alpha = 1.6732632423543772f;
    return x > 0.0f ? scale * x : scale * alpha * expm1f(x);
}

// Closed-form cubic B-spline (validated rounds 4-11 vs Cox-de-Boor).
struct Bsp { float w0, w1, w2, w3; int m; };
__device__ __forceinline__ Bsp bspline4(float x) {
    Bsp r;
    float tpos = (x + 2.2f) * 2.5f;
    float mf = floorf(tpos);
    r.m = (int)mf;
    float u = tpos - mf;
    float u2 = u * u, u3 = u2 * u, om = 1.0f - u;
    bool valid = (x >= -2.2f) && (r.m <= 10);
    float s = valid ? (1.0f / 6.0f) : 0.0f;
    r.w0 = om * om * om * s;
    r.w1 = (3.0f * u3 - 6.0f * u2 + 4.0f) * s;
    r.w2 = (-3.0f * u3 + 3.0f * u2 + 3.0f * u + 1.0f) * s;
    r.w3 = u3 * s;
    return r;
}
__device__ __forceinline__ float bsp_at(const Bsp& r, int g) {
    int d = r.m - g;
    float v = 0.0f;
    v = (d == 3) ? r.w0 : v;
    v = (d == 2) ? r.w1 : v;
    v = (d == 1) ? r.w2 : v;
    v = (d == 0) ? r.w3 : v;
    return v;
}

#define F4C(v, k) ((k)==0 ? (v).x : (k)==1 ? (v).y : (k)==2 ? (v).z : (v).w)

// ---------------------------------------------------------------------------
// K2: warp-specialized layer-1 GEMM.
// Stage layout: [A frag 18KB | B frag 18KB].
//   A: 4 K16 steps @ j*4096 (slot 16B) + silu @16384 (slot 8B).
//   B: 4 K16 steps @ j*4096 (slot 8B)  + silu @16384 (slot 4B).
// ---------------------------------------------------------------------------
__global__ void __launch_bounds__(512, 1) k2_mma(const float* __restrict__ x,
                                                const float* __restrict__ coef1,
                                                const float* __restrict__ sb1,
                                                const float* __restrict__ ssp1) {
    extern __shared__ __align__(16) char smem[];

    const int tid  = threadIdx.x;
    const int o0   = blockIdx.x * 128;
    const int split = blockIdx.y;
    const int ibase0 = split * IPC;

    if (tid >= 256) {
        // =================== PRODUCER (warps 8-15) ===================
        const int ptid = tid - 256;

        // A slot: one per producer thread (8 mt x 32 ln)
        const int a_mt = ptid >> 5, a_ln = ptid & 31;
        const int a_r  = a_ln >> 2, a_c = a_ln & 3;
        const uint32_t a_slotb = (uint32_t)(a_mt * 32 + a_ln) * 16;
        const int a_orow = o0 + a_mt * 16 + a_r;

        // B units: two per producer thread
        int b_row[2], b_c[2];
        uint32_t b_slotb[2];
#pragma unroll
        for (int p = 0; p < 2; p++) {
            int s = ptid + 256 * p;
            int nt = s >> 5, ln = s & 31;
            b_row[p]   = nt * 8 + (ln >> 2);
            b_c[p]     = ln & 3;
            b_slotb[p] = (uint32_t)(nt * 32 + ln) * 8;
        }

        float4 t0[4], t1[4];
        float  psp[4], psb[4];
        float  px[2][2];

        auto ldgA = [&](int ib) {
#pragma unroll
            for (int e = 0; e < 4; e++) {
                int o = a_orow + 8 * (e >> 1);
                int i = ib + 2 * a_c + (e & 1);
                int idx = o * IN_ + i;
                t0[e]  = ((const float4*)coef1)[idx * 2];
                t1[e]  = ((const float4*)coef1)[idx * 2 + 1];
                psp[e] = ssp1[idx];
                psb[e] = sb1[idx];
            }
        };
        auto ldgB = [&](int ib) {
#pragma unroll
            for (int p = 0; p < 2; p++) {
                px[p][0] = x[b_row[p] * IN_ + ib + 2 * b_c[p]];
                px[p][1] = x[b_row[p] * IN_ + ib + 2 * b_c[p] + 1];
            }
        };
        auto stsA = [&](uint32_t offA) {
            char* As = smem + offA;
#pragma unroll
            for (int j = 0; j < 4; j++) {
                const int g0 = 2 * j, g1 = 2 * j + 1;
                float v00, v01, v10, v11, q00, q01, q10, q11;
                if (g0 < 4) { v00 = F4C(t0[0], g0); v01 = F4C(t0[1], g0);
                              v10 = F4C(t0[2], g0); v11 = F4C(t0[3], g0); }
                else        { v00 = F4C(t1[0], g0 - 4); v01 = F4C(t1[1], g0 - 4);
                              v10 = F4C(t1[2], g0 - 4); v11 = F4C(t1[3], g0 - 4); }
                if (g1 < 4) { q00 = F4C(t0[0], g1); q01 = F4C(t0[1], g1);
                              q10 = F4C(t0[2], g1); q11 = F4C(t0[3], g1); }
                else        { q00 = F4C(t1[0], g1 - 4); q01 = F4C(t1[1], g1 - 4);
                              q10 = F4C(t1[2], g1 - 4); q11 = F4C(t1[3], g1 - 4); }
                uint4 u;
                u.x = packh2(psp[0] * v00, psp[1] * v01);
                u.y = packh2(psp[2] * v10, psp[3] * v11);
                u.z = packh2(psp[0] * q00, psp[1] * q01);
                u.w = packh2(psp[2] * q10, psp[3] * q11);
                *(uint4*)(As + j * 4096 + a_slotb) = u;
            }
            uint2 v;
            v.x = packh2(psb[0], psb[1]);
            v.y = packh2(psb[2], psb[3]);
            *(uint2*)(As + 16384 + (a_slotb >> 1)) = v;
        };
        auto prodB = [&](uint32_t offB) {
            char* Bb = smem + offB;
#pragma unroll
            for (int p = 0; p < 2; p++) {
                const uint32_t sb8 = b_slotb[p];
#pragma unroll
                for (int j = 0; j < 4; j++)
                    *(uint2*)(Bb + j * 4096 + sb8) = make_uint2(0u, 0u);
                Bsp q0 = bspline4(px[p][0]);
                Bsp q1 = bspline4(px[p][1]);
                float wa[4] = { q0.w0, q0.w1, q0.w2, q0.w3 };
                float wb[4] = { q1.w0, q1.w1, q1.w2, q1.w3 };
#pragma unroll
                for (int k = 0; k < 4; k++) {
                    int ga = q0.m - 3 + k;
                    if (ga >= 0 && ga <= 7)
                        *(uint16_t*)(Bb + (ga >> 1) * 4096 + sb8 + (ga & 1) * 4)     = h16(wa[k]);
                    int gb = q1.m - 3 + k;
                    if (gb >= 0 && gb <= 7)
                        *(uint16_t*)(Bb + (gb >> 1) * 4096 + sb8 + (gb & 1) * 4 + 2) = h16(wb[k]);
                }
                *(uint32_t*)(Bb + 16384 + (sb8 >> 1)) =
                    packh2(silu_f(px[p][0]), silu_f(px[p][1]));
            }
        };

        ldgA(ibase0); ldgB(ibase0);
        for (int t = 0; t < NCH; t++) {
            const uint32_t stg = (uint32_t)(t % 3) * STGB;
            stsA(stg);
            if (t + 1 < NCH) ldgA(ibase0 + (t + 1) * 8);
            prodB(stg + 18432);
            if (t + 1 < NCH) ldgB(ibase0 + (t + 1) * 8);
            BARS(1 + t % 3, 512);           // rendezvous: stage t ready
        }
        return;
    }

    // =================== CONSUMER (warps 0-7) ===================
    const int lane = tid & 31;
    const int wid  = tid >> 5;
    const int wm   = wid >> 2;          // 0..1 : 64 o per warp
    const int wn   = wid & 3;           // 0..3 : 32 b per warp

    float acc[4][4][4];
#pragma unroll
    for (int mi = 0; mi < 4; mi++)
#pragma unroll
        for (int ni = 0; ni < 4; ni++)
#pragma unroll
            for (int w = 0; w < 4; w++) acc[mi][ni][w] = 0.0f;

    for (int t = 0; t < NCH; t++) {
        BARS(1 + t % 3, 512);               // rendezvous: stage t ready
        const char* As = smem + (t % 3) * STGB;
        const char* Bb = As + 18432;
#pragma unroll
        for (int j = 0; j < 4; j++) {
            uint4 af[4];
            uint2 bf[4];
#pragma unroll
            for (int mi = 0; mi < 4; mi++)
                af[mi] = *(const uint4*)(As + j * 4096 + (((wm * 4 + mi) * 32 + lane) << 4));
#pragma unroll
            for (int ni = 0; ni < 4; ni++)
                bf[ni] = *(const uint2*)(Bb + j * 4096 + (((wn * 4 + ni) * 32 + lane) << 3));
#pragma unroll
            for (int mi = 0; mi < 4; mi++)
#pragma unroll
                for (int ni = 0; ni < 4; ni++) mma16(acc[mi][ni], af[mi], bf[ni]);
        }
        // silu K8 step
        uint2 af2[4];
        uint32_t bf2[4];
#pragma unroll
        for (int mi = 0; mi < 4; mi++)
            af2[mi] = *(const uint2*)(As + 16384 + (((wm * 4 + mi) * 32 + lane) << 3));
#pragma unroll
        for (int ni = 0; ni < 4; ni++)
            bf2[ni] = *(const uint32_t*)(Bb + 16384 + (((wn * 4 + ni) * 32 + lane) << 2));
#pragma unroll
        for (int mi = 0; mi < 4; mi++)
#pragma unroll
            for (int ni = 0; ni < 4; ni++) mma8h(acc[mi][ni], af2[mi], bf2[ni]);
    }

    // --- writeout (R9/R11-validated): transpose via smem (stages 0-1) ---
    {
        float* S = (float*)smem;            // 128 x 132 floats = 67.5KB (< 2 stages)
        const int r = lane >> 2, c = lane & 3;
#pragma unroll
        for (int mi = 0; mi < 4; mi++)
#pragma unroll
            for (int ni = 0; ni < 4; ni++)
#pragma unroll
                for (int w = 0; w < 4; w++) {
                    int o_l = (wm * 4 + mi) * 16 + r + 8 * (w >> 1);
                    int b_l = (wn * 4 + ni) * 8 + 2 * c + (w & 1);
                    S[b_l * SP + o_l] = acc[mi][ni][w];
                }
        BARS(7, 256);                       // consumer-only barrier
        float* Y = g_Y1p + split * (B_ * H_);
#pragma unroll
        for (int p = 0; p < 16; p++) {
            int idx = tid + 256 * p;
            int bb = idx >> 5, o4 = idx & 31;
            float4 v = *(float4*)&S[bb * SP + o4 * 4];
            *(float4*)&Y[bb * H_ + o0 + o4 * 4] = v;
        }
    }
}

// ---------------------------------------------------------------------------
// K3a: split reduction, 256 CTAs (validated round 5).
// ---------------------------------------------------------------------------
__global__ void __launch_bounds__(256) k3a_reduce() {
    __shared__ float4 sred[8][32];
    const int t = threadIdx.x, c = blockIdx.x;
    const int lane = t & 31, w = t >> 5;
    const int out = c * 32 + lane;
    const int b = out >> 6, o4 = out & 63;

    const float4* P = (const float4*)g_Y1p;
    float4 acc = make_float4(0.f, 0.f, 0.f, 0.f);
#pragma unroll
    for (int k = 0; k < 8; k++) {
        int s = w * 8 + k;
        float4 v = P[(s * B_ + b) * (H_ / 4) + o4];
        acc.x += v.x; acc.y += v.y; acc.z += v.z; acc.w += v.w;
    }
    sred[w][lane] = acc;
    __syncthreads();
    if (t < 32) {
        float4 a = sred[0][t];
#pragma unroll
        for (int j = 1; j < 8; j++) {
            float4 v = sred[j][t];
            a.x += v.x; a.y += v.y; a.z += v.z; a.w += v.w;
        }
        ((float4*)g_Y1)[c * 32 + t] = a;
    }
}

// ---------------------------------------------------------------------------
// K3b: layer 2, shfl reduction (validated round 5).
// ---------------------------------------------------------------------------
__global__ void __launch_bounds__(256) k3b_layer2(const float* __restrict__ coef2,
                                                 const float* __restrict__ sb2,
                                                 const float* __restrict__ ssp2,
                                                 float* __restrict__ out) {
    const int b = blockIdx.x;
    const int t = threadIdx.x;
    const int lane = t & 31, w = t >> 5;

    float h = selu_f(g_Y1[b * H_ + t]);
    Bsp bs = bspline4(h);
    float f0 = silu_f(h);
    float fb[8];
#pragma unroll
    for (int g = 0; g < 8; g++) fb[g] = bsp_at(bs, g);

    __shared__ float red[OUT_ * 8];
    float val[OUT_];
#pragma unroll
    for (int o = 0; o < OUT_; o++) {
        int e = o * H_ + t;
        float4 c0 = ((const float4*)coef2)[e * 2];
        float4 c1 = ((const float4*)coef2)[e * 2 + 1];
        float sp = ssp2[e];
        float spline = fb[0] * c0.x + fb[1] * c0.y + fb[2] * c0.z + fb[3] * c0.w
                     + fb[4] * c1.x + fb[5] * c1.y + fb[6] * c1.z + fb[7] * c1.w;
        val[o] = sb2[e] * f0 + sp * spline;
    }
#pragma unroll
    for (int o = 0; o < OUT_; o++) {
#pragma unroll
        for (int off = 16; off > 0; off >>= 1)
            val[o] += __shfl_down_sync(0xFFFFFFFFu, val[o], off);
    }
    if (lane == 0) {
#pragma unroll
        for (int o = 0; o < OUT_; o++) red[o * 8 + w] = val[o];
    }
    __syncthreads();
    if (t < OUT_) {
        float s = 0.0f;
#pragma unroll
        for (int j = 0; j < 8; j++) s += red[t * 8 + j];
        out[b * OUT_ + t] = s;
    }
}

// ---------------------------------------------------------------------------
extern "C" void kernel_launch(void* const* d_in, const int* in_sizes, int n_in,
                              void* d_out, int out_size) {
    const float* x     = (const float*)d_in[0];
    const float* coef1 = (const float*)d_in[1];
    const float* sb1   = (const float*)d_in[2];
    const float* ssp1  = (const float*)d_in[3];
    const float* coef2 = (const float*)d_in[4];
    const float* sb2   = (const float*)d_in[5];
    const float* ssp2  = (const float*)d_in[6];
    float* out = (float*)d_out;

    cudaFuncSetAttribute(k2_mma, cudaFuncAttributeMaxDynamicSharedMemorySize, SMEM_TOTAL);
    k2_mma<<<dim3(2, KSPLIT), 512, SMEM_TOTAL>>>(x, coef1, sb1, ssp1);
    k3a_reduce<<<(B_ * H_) / (32 * 4), 256>>>();
    k3b_layer2<<<B_, 256>>>(coef2, sb2, ssp2, out);
}

// round 13
// speedup vs baseline: 1.2847x; 1.0813x over previous
#include <cuda_runtime.h>
#include <cuda_fp16.h>
#include <cstdint>

// ---------------------------------------------------------------------------
// KAN 2-layer fused, round 13: warp-specialized K2 with row-major fp16 tiles
// + ldmatrix consumers (kills producer LDG divergence, the round-4..12 L1 wall).
//   512 threads: warps 0-7 consume (m16n8k16/k8 fp16 MMA via ldmatrix),
//   warps 8-15 produce (coalesced LDG -> scale -> conflict-free STS).
//   Tiles: A = fp16[o 128][k 72], B = fp16[b 128][k 72]; k = i*8+g, 64+i silu.
//   3-stage ring (36KB/stage), rendezvous bar.sync per stage (R12-validated).
//   K2 CTA: M=128 (o) x N=128 (b) x K=432; grid (2 o-tiles x 64 splits).
// ---------------------------------------------------------------------------

#define B_     128
#define IN_    3072
#define H_     256
#define OUT_   10
#define KSPLIT 64
#define IPC    48
#define NCH    6
#define ROWB   144          // bytes per tile row (72 fp16): 36 words = 4 mod 32
#define TILEB  18432        // 128 rows * 144 B
#define STGB   36864        // A tile + B tile
#define SMEM_TOTAL (3 * STGB)
#define SP     132

__device__ float g_Y1p[KSPLIT * B_ * H_];
__device__ float g_Y1[B_ * H_];

// ---- helpers ---------------------------------------------------------------
__device__ __forceinline__ uint32_t smem_u32(const void* p) {
    uint32_t a;
    asm("{ .reg .u64 t; cvta.to.shared.u64 t, %1; cvt.u32.u64 %0, t; }" : "=r"(a) : "l"(p));
    return a;
}
__device__ __forceinline__ uint32_t packh2(float lo, float hi) {
    __half2 h = __floats2half2_rn(lo, hi);
    return *(uint32_t*)&h;
}
__device__ __forceinline__ uint16_t h16(float v) {
    __half h = __float2half_rn(v);
    return __half_as_ushort(h);
}
__device__ __forceinline__ uint4 ldsm_x4(uint32_t a) {
    uint4 r;
    asm volatile("ldmatrix.sync.aligned.m8n8.x4.shared.b16 {%0,%1,%2,%3}, [%4];"
        : "=r"(r.x), "=r"(r.y), "=r"(r.z), "=r"(r.w) : "r"(a));
    return r;
}
__device__ __forceinline__ uint2 ldsm_x2(uint32_t a) {
    uint2 r;
    asm volatile("ldmatrix.sync.aligned.m8n8.x2.shared.b16 {%0,%1}, [%2];"
        : "=r"(r.x), "=r"(r.y) : "r"(a));
    return r;
}
__device__ __forceinline__ uint32_t ldsm_x1(uint32_t a) {
    uint32_t r;
    asm volatile("ldmatrix.sync.aligned.m8n8.x1.shared.b16 {%0}, [%1];"
        : "=r"(r) : "r"(a));
    return r;
}
__device__ __forceinline__ void mma16(float d[4], const uint4& a, const uint2& b) {
    asm volatile("mma.sync.aligned.m16n8k16.row.col.f32.f16.f16.f32 "
        "{%0,%1,%2,%3}, {%4,%5,%6,%7}, {%8,%9}, {%0,%1,%2,%3};"
        : "+f"(d[0]), "+f"(d[1]), "+f"(d[2]), "+f"(d[3])
        : "r"(a.x), "r"(a.y), "r"(a.z), "r"(a.w), "r"(b.x), "r"(b.y));
}
__device__ __forceinline__ void mma8h(float d[4], const uint2& a, uint32_t b) {
    asm volatile("mma.sync.aligned.m16n8k8.row.col.f32.f16.f16.f32 "
        "{%0,%1,%2,%3}, {%4,%5}, {%6}, {%0,%1,%2,%3};"
        : "+f"(d[0]), "+f"(d[1]), "+f"(d[2]), "+f"(d[3])
        : "r"(a.x), "r"(a.y), "r"(b));
}
#define BARS(id, cnt) asm volatile("bar.sync %0, %1;" :: "r"(id), "r"(cnt) : "memory")

__device__ __forceinline__ float silu_f(float x) { return x / (1.0f + __expf(-x)); }
__device__ __forceinline__ float selu_f(float x) {
    const float scale = 1.0507009873554805f;
    const float alpha = 1.6732632423543772f;
    return x > 0.0f ? scale * x : scale * alpha * expm1f(x);
}

// Closed-form cubic B-spline (validated rounds 4-12 vs Cox-de-Boor).
struct Bsp { float w0, w1, w2, w3; int m; };
__device__ __forceinline__ Bsp bspline4(float x) {
    Bsp r;
    float tpos = (x + 2.2f) * 2.5f;
    float mf = floorf(tpos);
    r.m = (int)mf;
    float u = tpos - mf;
    float u2 = u * u, u3 = u2 * u, om = 1.0f - u;
    bool valid = (x >= -2.2f) && (r.m <= 10);
    float s = valid ? (1.0f / 6.0f) : 0.0f;
    r.w0 = om * om * om * s;
    r.w1 = (3.0f * u3 - 6.0f * u2 + 4.0f) * s;
    r.w2 = (-3.0f * u3 + 3.0f * u2 + 3.0f * u + 1.0f) * s;
    r.w3 = u3 * s;
    return r;
}
__device__ __forceinline__ float bsp_at(const Bsp& r, int g) {
    int d = r.m - g;
    float v = 0.0f;
    v = (d == 3) ? r.w0 : v;
    v = (d == 2) ? r.w1 : v;
    v = (d == 1) ? r.w2 : v;
    v = (d == 0) ? r.w3 : v;
    return v;
}

// ---------------------------------------------------------------------------
// K2: warp-specialized layer-1 GEMM, row-major tiles + ldmatrix.
// ---------------------------------------------------------------------------
__global__ void __launch_bounds__(512, 1) k2_mma(const float* __restrict__ x,
                                                const float* __restrict__ coef1,
                                                const float* __restrict__ sb1,
                                                const float* __restrict__ ssp1) {
    extern __shared__ __align__(16) char smem[];

    const int tid  = threadIdx.x;
    const int o0   = blockIdx.x * 128;
    const int split = blockIdx.y;
    const int ibase0 = split * IPC;

    if (tid >= 256) {
        // =================== PRODUCER (warps 8-15) ===================
        const int ptid = tid - 256;

        float4 pc[8];
        float  psp[8], psb[4], px[4];

        auto ldgA = [&](int ib) {
#pragma unroll
            for (int k = 0; k < 8; k++) {           // coalesced: f consecutive
                int f = ptid + 256 * k;
                int o = f >> 4, i2 = (f >> 1) & 7, h = f & 1;
                int e = (o0 + o) * IN_ + ib + i2;
                pc[k]  = ((const float4*)coef1)[e * 2 + h];
                psp[k] = ssp1[e];
            }
#pragma unroll
            for (int k = 0; k < 4; k++) {           // sb for silu plane
                int f = ptid + 256 * k;
                int o = f >> 3, i2 = f & 7;
                psb[k] = sb1[(o0 + o) * IN_ + ib + i2];
            }
        };
        auto ldgB = [&](int ib) {
#pragma unroll
            for (int u = 0; u < 4; u++) {
                int f = ptid + 256 * u;
                int b = f >> 3, i2 = f & 7;
                px[u] = x[b * IN_ + ib + i2];
            }
        };
        auto stsA = [&](char* As) {
#pragma unroll
            for (int k = 0; k < 8; k++) {
                int f = ptid + 256 * k;
                int o = f >> 4, i2 = (f >> 1) & 7, h = f & 1;
                uint2 v;
                v.x = packh2(psp[k] * pc[k].x, psp[k] * pc[k].y);
                v.y = packh2(psp[k] * pc[k].z, psp[k] * pc[k].w);
                *(uint2*)(As + o * ROWB + i2 * 16 + h * 8) = v;   // conflict-free
            }
#pragma unroll
            for (int k = 0; k < 4; k++) {
                int f = ptid + 256 * k;
                int o = f >> 3, i2 = f & 7;
                *(uint16_t*)(As + o * ROWB + 128 + i2 * 2) = h16(psb[k]);
            }
        };
        auto prodB = [&](char* Bb) {
#pragma unroll
            for (int u = 0; u < 4; u++) {
                int f = ptid + 256 * u;
                int b = f >> 3, i2 = f & 7;
                char* row = Bb + b * ROWB;
                *(uint4*)(row + i2 * 16) = make_uint4(0u, 0u, 0u, 0u);
                Bsp q = bspline4(px[u]);
                float w[4] = { q.w0, q.w1, q.w2, q.w3 };
#pragma unroll
                for (int kk = 0; kk < 4; kk++) {
                    int g = q.m - 3 + kk;
                    if (g >= 0 && g <= 7)
                        *(uint16_t*)(row + i2 * 16 + g * 2) = h16(w[kk]);
                }
                *(uint16_t*)(row + 128 + i2 * 2) = h16(silu_f(px[u]));
            }
        };

        ldgA(ibase0); ldgB(ibase0);
        for (int t = 0; t < NCH; t++) {
            char* stg = smem + (t % 3) * STGB;
            stsA(stg);
            if (t + 1 < NCH) ldgA(ibase0 + (t + 1) * 8);
            prodB(stg + TILEB);
            if (t + 1 < NCH) ldgB(ibase0 + (t + 1) * 8);
            BARS(1 + t % 3, 512);
        }
        return;
    }

    // =================== CONSUMER (warps 0-7) ===================
    const int lane = tid & 31;
    const int wid  = tid >> 5;
    const int wm   = wid >> 2;          // 0..1 : 64 o per warp
    const int wn   = wid & 3;           // 0..3 : 32 b per warp

    float acc[4][4][4];
#pragma unroll
    for (int mi = 0; mi < 4; mi++)
#pragma unroll
        for (int ni = 0; ni < 4; ni++)
#pragma unroll
            for (int w = 0; w < 4; w++) acc[mi][ni][w] = 0.0f;

    const uint32_t sb32 = smem_u32(smem);
    const uint32_t laneA  = ((lane & 7) + ((lane >> 3) & 1) * 8) * ROWB
                          + ((lane >> 4) & 1) * 16;
    const uint32_t laneAs = ((lane & 7) + ((lane >> 3) & 1) * 8) * ROWB;
    const uint32_t laneB  = (lane & 7) * ROWB + ((lane >> 3) & 1) * 16;
    const uint32_t laneBs = (lane & 7) * ROWB;
    uint32_t rowA[4], rowB[4];
#pragma unroll
    for (int mi = 0; mi < 4; mi++) rowA[mi] = (uint32_t)((wm * 4 + mi) * 16) * ROWB;
#pragma unroll
    for (int ni = 0; ni < 4; ni++) rowB[ni] = TILEB + (uint32_t)((wn * 4 + ni) * 8) * ROWB;

    for (int t = 0; t < NCH; t++) {
        BARS(1 + t % 3, 512);
        const uint32_t stg = sb32 + (uint32_t)(t % 3) * STGB;
#pragma unroll
        for (int j = 0; j < 4; j++) {
            uint4 af[4];
            uint2 bf[4];
#pragma unroll
            for (int mi = 0; mi < 4; mi++)
                af[mi] = ldsm_x4(stg + rowA[mi] + laneA + 32 * j);
#pragma unroll
            for (int ni = 0; ni < 4; ni++)
                bf[ni] = ldsm_x2(stg + rowB[ni] + laneB + 32 * j);
#pragma unroll
            for (int mi = 0; mi < 4; mi++)
#pragma unroll
                for (int ni = 0; ni < 4; ni++) mma16(acc[mi][ni], af[mi], bf[ni]);
        }
        // silu K8 step (k = 64..71)
        uint2 af2[4];
        uint32_t bf2[4];
#pragma unroll
        for (int mi = 0; mi < 4; mi++)
            af2[mi] = ldsm_x2(stg + rowA[mi] + laneAs + 128);
#pragma unroll
        for (int ni = 0; ni < 4; ni++)
            bf2[ni] = ldsm_x1(stg + rowB[ni] + laneBs + 128);
#pragma unroll
        for (int mi = 0; mi < 4; mi++)
#pragma unroll
            for (int ni = 0; ni < 4; ni++) mma8h(acc[mi][ni], af2[mi], bf2[ni]);
    }

    // --- writeout (validated): transpose via smem (stages 0-1 region) ---
    {
        float* S = (float*)smem;            // 128 x 132 = 67584 B < 73728
        const int r = lane >> 2, c = lane & 3;
#pragma unroll
        for (int mi = 0; mi < 4; mi++)
#pragma unroll
            for (int ni = 0; ni < 4; ni++)
#pragma unroll
                for (int w = 0; w < 4; w++) {
                    int o_l = (wm * 4 + mi) * 16 + r + 8 * (w >> 1);
                    int b_l = (wn * 4 + ni) * 8 + 2 * c + (w & 1);
                    S[b_l * SP + o_l] = acc[mi][ni][w];
                }
        BARS(7, 256);
        float* Y = g_Y1p + split * (B_ * H_);
#pragma unroll
        for (int p = 0; p < 16; p++) {
            int idx = tid + 256 * p;
            int bb = idx >> 5, o4 = idx & 31;
            float4 v = *(float4*)&S[bb * SP + o4 * 4];
            *(float4*)&Y[bb * H_ + o0 + o4 * 4] = v;
        }
    }
}

// ---------------------------------------------------------------------------
// K3a: split reduction, 256 CTAs (validated round 5).
// ---------------------------------------------------------------------------
__global__ void __launch_bounds__(256) k3a_reduce() {
    __shared__ float4 sred[8][32];
    const int t = threadIdx.x, c = blockIdx.x;
    const int lane = t & 31, w = t >> 5;
    const int out = c * 32 + lane;
    const int b = out >> 6, o4 = out & 63;

    const float4* P = (const float4*)g_Y1p;
    float4 acc = make_float4(0.f, 0.f, 0.f, 0.f);
#pragma unroll
    for (int k = 0; k < 8; k++) {
        int s = w * 8 + k;
        float4 v = P[(s * B_ + b) * (H_ / 4) + o4];
        acc.x += v.x; acc.y += v.y; acc.z += v.z; acc.w += v.w;
    }
    sred[w][lane] = acc;
    __syncthreads();
    if (t < 32) {
        float4 a = sred[0][t];
#pragma unroll
        for (int j = 1; j < 8; j++) {
            float4 v = sred[j][t];
            a.x += v.x; a.y += v.y; a.z += v.z; a.w += v.w;
        }
        ((float4*)g_Y1)[c * 32 + t] = a;
    }
}

// ---------------------------------------------------------------------------
// K3b: layer 2, shfl reduction (validated round 5).
// ---------------------------------------------------------------------------
__global__ void __launch_bounds__(256) k3b_layer2(const float* __restrict__ coef2,
                                                 const float* __restrict__ sb2,
                                                 const float* __restrict__ ssp2,
                                                 float* __restrict__ out) {
    const int b = blockIdx.x;
    const int t = threadIdx.x;
    const int lane = t & 31, w = t >> 5;

    float h = selu_f(g_Y1[b * H_ + t]);
    Bsp bs = bspline4(h);
    float f0 = silu_f(h);
    float fb[8];
#pragma unroll
    for (int g = 0; g < 8; g++) fb[g] = bsp_at(bs, g);

    __shared__ float red[OUT_ * 8];
    float val[OUT_];
#pragma unroll
    for (int o = 0; o < OUT_; o++) {
        int e = o * H_ + t;
        float4 c0 = ((const float4*)coef2)[e * 2];
        float4 c1 = ((const float4*)coef2)[e * 2 + 1];
        float sp = ssp2[e];
        float spline = fb[0] * c0.x + fb[1] * c0.y + fb[2] * c0.z + fb[3] * c0.w
                     + fb[4] * c1.x + fb[5] * c1.y + fb[6] * c1.z + fb[7] * c1.w;
        val[o] = sb2[e] * f0 + sp * spline;
    }
#pragma unroll
    for (int o = 0; o < OUT_; o++) {
#pragma unroll
        for (int off = 16; off > 0; off >>= 1)
            val[o] += __shfl_down_sync(0xFFFFFFFFu, val[o], off);
    }
    if (lane == 0) {
#pragma unroll
        for (int o = 0; o < OUT_; o++) red[o * 8 + w] = val[o];
    }
    __syncthreads();
    if (t < OUT_) {
        float s = 0.0f;
#pragma unroll
        for (int j = 0; j < 8; j++) s += red[t * 8 + j];
        out[b * OUT_ + t] = s;
    }
}

// ---------------------------------------------------------------------------
extern "C" void kernel_launch(void* const* d_in, const int* in_sizes, int n_in,
                              void* d_out, int out_size) {
    const float* x     = (const float*)d_in[0];
    const float* coef1 = (const float*)d_in[1];
    const float* sb1   = (const float*)d_in[2];
    const float* ssp1  = (const float*)d_in[3];
    const float* coef2 = (const float*)d_in[4];
    const float* sb2   = (const float*)d_in[5];
    const float* ssp2  = (const float*)d_in[6];
    float* out = (float*)d_out;

    cudaFuncSetAttribute(k2_mma, cudaFuncAttributeMaxDynamicSharedMemorySize, SMEM_TOTAL);
    k2_mma<<<dim3(2, KSPLIT), 512, SMEM_TOTAL>>>(x, coef1, sb1, ssp1);
    k3a_reduce<<<(B_ * H_) / (32 * 4), 256>>>();
    k3b_layer2<<<B_, 256>>>(coef2, sb2, ssp2, out);
}

// round 14
// speedup vs baseline: 1.3900x; 1.0819x over previous
#include <cuda_runtime.h>
#include <cuda_fp16.h>
#include <cstdint>

// ---------------------------------------------------------------------------
// KAN 2-layer fused, round 14: R13 (warp-specialized, row-major fp16 tiles,
// ldmatrix) + decoupled arrive/wait barriers (true 3-deep ring) + fp16
// layer-1 partials (halved partial traffic).
//   512 threads: warps 0-7 consume, warps 8-15 produce.
//   Full barriers 1-3 (producer arrives, consumer syncs);
//   free barriers 4-6 (consumer arrives, producer syncs; skipped t<3).
//   K2 CTA: M=128 (o) x N=128 (b) x K=432; grid (2 o-tiles x 64 splits).
// ---------------------------------------------------------------------------

#define B_     128
#define IN_    3072
#define H_     256
#define OUT_   10
#define KSPLIT 64
#define IPC    48
#define NCH    6
#define ROWB   144          // bytes per tile row (72 fp16)
#define TILEB  18432        // 128 rows * 144 B
#define STGB   36864        // A tile + B tile
#define SMEM_TOTAL (3 * STGB)
#define SP     132

__device__ __half g_Y1ph[KSPLIT * B_ * H_];   // layer-1 partials, fp16 (4MB)
__device__ float  g_Y1[B_ * H_];

// ---- helpers ---------------------------------------------------------------
__device__ __forceinline__ uint32_t smem_u32(const void* p) {
    uint32_t a;
    asm("{ .reg .u64 t; cvta.to.shared.u64 t, %1; cvt.u32.u64 %0, t; }" : "=r"(a) : "l"(p));
    return a;
}
__device__ __forceinline__ uint32_t packh2(float lo, float hi) {
    __half2 h = __floats2half2_rn(lo, hi);
    return *(uint32_t*)&h;
}
__device__ __forceinline__ uint16_t h16(float v) {
    __half h = __float2half_rn(v);
    return __half_as_ushort(h);
}
__device__ __forceinline__ uint4 ldsm_x4(uint32_t a) {
    uint4 r;
    asm volatile("ldmatrix.sync.aligned.m8n8.x4.shared.b16 {%0,%1,%2,%3}, [%4];"
        : "=r"(r.x), "=r"(r.y), "=r"(r.z), "=r"(r.w) : "r"(a));
    return r;
}
__device__ __forceinline__ uint2 ldsm_x2(uint32_t a) {
    uint2 r;
    asm volatile("ldmatrix.sync.aligned.m8n8.x2.shared.b16 {%0,%1}, [%2];"
        : "=r"(r.x), "=r"(r.y) : "r"(a));
    return r;
}
__device__ __forceinline__ uint32_t ldsm_x1(uint32_t a) {
    uint32_t r;
    asm volatile("ldmatrix.sync.aligned.m8n8.x1.shared.b16 {%0}, [%1];"
        : "=r"(r) : "r"(a));
    return r;
}
__device__ __forceinline__ void mma16(float d[4], const uint4& a, const uint2& b) {
    asm volatile("mma.sync.aligned.m16n8k16.row.col.f32.f16.f16.f32 "
        "{%0,%1,%2,%3}, {%4,%5,%6,%7}, {%8,%9}, {%0,%1,%2,%3};"
        : "+f"(d[0]), "+f"(d[1]), "+f"(d[2]), "+f"(d[3])
        : "r"(a.x), "r"(a.y), "r"(a.z), "r"(a.w), "r"(b.x), "r"(b.y));
}
__device__ __forceinline__ void mma8h(float d[4], const uint2& a, uint32_t b) {
    asm volatile("mma.sync.aligned.m16n8k8.row.col.f32.f16.f16.f32 "
        "{%0,%1,%2,%3}, {%4,%5}, {%6}, {%0,%1,%2,%3};"
        : "+f"(d[0]), "+f"(d[1]), "+f"(d[2]), "+f"(d[3])
        : "r"(a.x), "r"(a.y), "r"(b));
}
#define BARS(id, cnt) asm volatile("bar.sync %0, %1;"   :: "r"(id), "r"(cnt) : "memory")
#define BARA(id, cnt) asm volatile("bar.arrive %0, %1;" :: "r"(id), "r"(cnt) : "memory")

__device__ __forceinline__ float silu_f(float x) { return x / (1.0f + __expf(-x)); }
__device__ __forceinline__ float selu_f(float x) {
    const float scale = 1.0507009873554805f;
    const float alpha = 1.6732632423543772f;
    return x > 0.0f ? scale * x : scale * alpha * expm1f(x);
}

// Closed-form cubic B-spline (validated rounds 4-13 vs Cox-de-Boor).
struct Bsp { float w0, w1, w2, w3; int m; };
__device__ __forceinline__ Bsp bspline4(float x) {
    Bsp r;
    float tpos = (x + 2.2f) * 2.5f;
    float mf = floorf(tpos);
    r.m = (int)mf;
    float u = tpos - mf;
    float u2 = u * u, u3 = u2 * u, om = 1.0f - u;
    bool valid = (x >= -2.2f) && (r.m <= 10);
    float s = valid ? (1.0f / 6.0f) : 0.0f;
    r.w0 = om * om * om * s;
    r.w1 = (3.0f * u3 - 6.0f * u2 + 4.0f) * s;
    r.w2 = (-3.0f * u3 + 3.0f * u2 + 3.0f * u + 1.0f) * s;
    r.w3 = u3 * s;
    return r;
}
__device__ __forceinline__ float bsp_at(const Bsp& r, int g) {
    int d = r.m - g;
    float v = 0.0f;
    v = (d == 3) ? r.w0 : v;
    v = (d == 2) ? r.w1 : v;
    v = (d == 1) ? r.w2 : v;
    v = (d == 0) ? r.w3 : v;
    return v;
}

// ---------------------------------------------------------------------------
// K2: warp-specialized layer-1 GEMM, decoupled 3-stage ring.
// ---------------------------------------------------------------------------
__global__ void __launch_bounds__(512, 1) k2_mma(const float* __restrict__ x,
                                                const float* __restrict__ coef1,
                                                const float* __restrict__ sb1,
                                                const float* __restrict__ ssp1) {
    extern __shared__ __align__(16) char smem[];

    const int tid  = threadIdx.x;
    const int o0   = blockIdx.x * 128;
    const int split = blockIdx.y;
    const int ibase0 = split * IPC;

    if (tid >= 256) {
        // =================== PRODUCER (warps 8-15) ===================
        const int ptid = tid - 256;

        float4 pc[8];
        float  psp[8], psb[4], px[4];

        auto ldgA = [&](int ib) {
#pragma unroll
            for (int k = 0; k < 8; k++) {           // coalesced
                int f = ptid + 256 * k;
                int o = f >> 4, i2 = (f >> 1) & 7, h = f & 1;
                int e = (o0 + o) * IN_ + ib + i2;
                pc[k]  = ((const float4*)coef1)[e * 2 + h];
                psp[k] = ssp1[e];
            }
#pragma unroll
            for (int k = 0; k < 4; k++) {
                int f = ptid + 256 * k;
                int o = f >> 3, i2 = f & 7;
                psb[k] = sb1[(o0 + o) * IN_ + ib + i2];
            }
        };
        auto ldgB = [&](int ib) {
#pragma unroll
            for (int u = 0; u < 4; u++) {
                int f = ptid + 256 * u;
                int b = f >> 3, i2 = f & 7;
                px[u] = x[b * IN_ + ib + i2];
            }
        };
        auto stsA = [&](char* As) {
#pragma unroll
            for (int k = 0; k < 8; k++) {
                int f = ptid + 256 * k;
                int o = f >> 4, i2 = (f >> 1) & 7, h = f & 1;
                uint2 v;
                v.x = packh2(psp[k] * pc[k].x, psp[k] * pc[k].y);
                v.y = packh2(psp[k] * pc[k].z, psp[k] * pc[k].w);
                *(uint2*)(As + o * ROWB + i2 * 16 + h * 8) = v;
            }
#pragma unroll
            for (int k = 0; k < 4; k++) {
                int f = ptid + 256 * k;
                int o = f >> 3, i2 = f & 7;
                *(uint16_t*)(As + o * ROWB + 128 + i2 * 2) = h16(psb[k]);
            }
        };
        auto prodB = [&](char* Bb) {
#pragma unroll
            for (int u = 0; u < 4; u++) {
                int f = ptid + 256 * u;
                int b = f >> 3, i2 = f & 7;
                char* row = Bb + b * ROWB;
                *(uint4*)(row + i2 * 16) = make_uint4(0u, 0u, 0u, 0u);
                Bsp q = bspline4(px[u]);
                float w[4] = { q.w0, q.w1, q.w2, q.w3 };
#pragma unroll
                for (int kk = 0; kk < 4; kk++) {
                    int g = q.m - 3 + kk;
                    if (g >= 0 && g <= 7)
                        *(uint16_t*)(row + i2 * 16 + g * 2) = h16(w[kk]);
                }
                *(uint16_t*)(row + 128 + i2 * 2) = h16(silu_f(px[u]));
            }
        };

        ldgA(ibase0); ldgB(ibase0);
        for (int t = 0; t < NCH; t++) {
            if (t >= 3) BARS(4 + t % 3, 512);   // wait: stage free (consumed t-3)
            char* stg = smem + (t % 3) * STGB;
            stsA(stg);
            if (t + 1 < NCH) ldgA(ibase0 + (t + 1) * 8);
            prodB(stg + TILEB);
            if (t + 1 < NCH) ldgB(ibase0 + (t + 1) * 8);
            BARA(1 + t % 3, 512);               // signal: stage t full
        }
        return;
    }

    // =================== CONSUMER (warps 0-7) ===================
    const int lane = tid & 31;
    const int wid  = tid >> 5;
    const int wm   = wid >> 2;          // 0..1 : 64 o per warp
    const int wn   = wid & 3;           // 0..3 : 32 b per warp

    float acc[4][4][4];
#pragma unroll
    for (int mi = 0; mi < 4; mi++)
#pragma unroll
        for (int ni = 0; ni < 4; ni++)
#pragma unroll
            for (int w = 0; w < 4; w++) acc[mi][ni][w] = 0.0f;

    const uint32_t sb32 = smem_u32(smem);
    const uint32_t laneA  = ((lane & 7) + ((lane >> 3) & 1) * 8) * ROWB
                          + ((lane >> 4) & 1) * 16;
    const uint32_t laneAs = ((lane & 7) + ((lane >> 3) & 1) * 8) * ROWB;
    const uint32_t laneB  = (lane & 7) * ROWB + ((lane >> 3) & 1) * 16;
    const uint32_t laneBs = (lane & 7) * ROWB;
    uint32_t rowA[4], rowB[4];
#pragma unroll
    for (int mi = 0; mi < 4; mi++) rowA[mi] = (uint32_t)((wm * 4 + mi) * 16) * ROWB;
#pragma unroll
    for (int ni = 0; ni < 4; ni++) rowB[ni] = TILEB + (uint32_t)((wn * 4 + ni) * 8) * ROWB;

    for (int t = 0; t < NCH; t++) {
        BARS(1 + t % 3, 512);                   // wait: stage t full
        const uint32_t stg = sb32 + (uint32_t)(t % 3) * STGB;
#pragma unroll
        for (int j = 0; j < 4; j++) {
            uint4 af[4];
            uint2 bf[4];
#pragma unroll
            for (int mi = 0; mi < 4; mi++)
                af[mi] = ldsm_x4(stg + rowA[mi] + laneA + 32 * j);
#pragma unroll
            for (int ni = 0; ni < 4; ni++)
                bf[ni] = ldsm_x2(stg + rowB[ni] + laneB + 32 * j);
#pragma unroll
            for (int mi = 0; mi < 4; mi++)
#pragma unroll
                for (int ni = 0; ni < 4; ni++) mma16(acc[mi][ni], af[mi], bf[ni]);
        }
        // silu K8 step (k = 64..71)
        uint2 af2[4];
        uint32_t bf2[4];
#pragma unroll
        for (int mi = 0; mi < 4; mi++)
            af2[mi] = ldsm_x2(stg + rowA[mi] + laneAs + 128);
#pragma unroll
        for (int ni = 0; ni < 4; ni++)
            bf2[ni] = ldsm_x1(stg + rowB[ni] + laneBs + 128);
#pragma unroll
        for (int mi = 0; mi < 4; mi++)
#pragma unroll
            for (int ni = 0; ni < 4; ni++) mma8h(acc[mi][ni], af2[mi], bf2[ni]);
        BARA(4 + t % 3, 512);                   // signal: stage t free
    }

    // --- writeout: transpose via smem, pack fp16, coalesced 8B stores ---
    {
        float* S = (float*)smem;            // 128 x 132 floats = 67584 B
        const int r = lane >> 2, c = lane & 3;
#pragma unroll
        for (int mi = 0; mi < 4; mi++)
#pragma unroll
            for (int ni = 0; ni < 4; ni++)
#pragma unroll
                for (int w = 0; w < 4; w++) {
                    int o_l = (wm * 4 + mi) * 16 + r + 8 * (w >> 1);
                    int b_l = (wn * 4 + ni) * 8 + 2 * c + (w & 1);
                    S[b_l * SP + o_l] = acc[mi][ni][w];
                }
        BARS(7, 256);                       // consumer-only barrier
        __half* Yh = g_Y1ph + split * (B_ * H_);
#pragma unroll
        for (int p = 0; p < 16; p++) {
            int idx = tid + 256 * p;
            int bb = idx >> 5, o4 = idx & 31;
            float4 v = *(float4*)&S[bb * SP + o4 * 4];
            uint2 u;
            u.x = packh2(v.x, v.y);
            u.y = packh2(v.z, v.w);
            *(uint2*)(Yh + bb * H_ + o0 + o4 * 4) = u;
        }
    }
}

// ---------------------------------------------------------------------------
// K3a: split reduction over fp16 partials, 256 CTAs.
// ---------------------------------------------------------------------------
__global__ void __launch_bounds__(256) k3a_reduce() {
    __shared__ float4 sred[8][32];
    const int t = threadIdx.x, c = blockIdx.x;
    const int lane = t & 31, w = t >> 5;
    const int out = c * 32 + lane;            // 4-o group index: (b, o4)
    const int b = out >> 6, o4 = out & 63;

    const uint2* P = (const uint2*)g_Y1ph;    // 4 halves per uint2
    float4 acc = make_float4(0.f, 0.f, 0.f, 0.f);
#pragma unroll
    for (int k = 0; k < 8; k++) {
        int s = w * 8 + k;
        uint2 u = P[(s * B_ + b) * (H_ / 4) + o4];
        float2 f0 = __half22float2(*reinterpret_cast<__half2*>(&u.x));
        float2 f1 = __half22float2(*reinterpret_cast<__half2*>(&u.y));
        acc.x += f0.x; acc.y += f0.y; acc.z += f1.x; acc.w += f1.y;
    }
    sred[w][lane] = acc;
    __syncthreads();
    if (t < 32) {
        float4 a = sred[0][t];
#pragma unroll
        for (int j = 1; j < 8; j++) {
            float4 v = sred[j][t];
            a.x += v.x; a.y += v.y; a.z += v.z; a.w += v.w;
        }
        ((float4*)g_Y1)[c * 32 + t] = a;
    }
}

// ---------------------------------------------------------------------------
// K3b: layer 2, shfl reduction (validated round 5).
// ---------------------------------------------------------------------------
__global__ void __launch_bounds__(256) k3b_layer2(const float* __restrict__ coef2,
                                                 const float* __restrict__ sb2,
                                                 const float* __restrict__ ssp2,
                                                 float* __restrict__ out) {
    const int b = blockIdx.x;
    const int t = threadIdx.x;
    const int lane = t & 31, w = t >> 5;

    float h = selu_f(g_Y1[b * H_ + t]);
    Bsp bs = bspline4(h);
    float f0 = silu_f(h);
    float fb[8];
#pragma unroll
    for (int g = 0; g < 8; g++) fb[g] = bsp_at(bs, g);

    __shared__ float red[OUT_ * 8];
    float val[OUT_];
#pragma unroll
    for (int o = 0; o < OUT_; o++) {
        int e = o * H_ + t;
        float4 c0 = ((const float4*)coef2)[e * 2];
        float4 c1 = ((const float4*)coef2)[e * 2 + 1];
        float sp = ssp2[e];
        float spline = fb[0] * c0.x + fb[1] * c0.y + fb[2] * c0.z + fb[3] * c0.w
                     + fb[4] * c1.x + fb[5] * c1.y + fb[6] * c1.z + fb[7] * c1.w;
        val[o] = sb2[e] * f0 + sp * spline;
    }
#pragma unroll
    for (int o = 0; o < OUT_; o++) {
#pragma unroll
        for (int off = 16; off > 0; off >>= 1)
            val[o] += __shfl_down_sync(0xFFFFFFFFu, val[o], off);
    }
    if (lane == 0) {
#pragma unroll
        for (int o = 0; o < OUT_; o++) red[o * 8 + w] = val[o];
    }
    __syncthreads();
    if (t < OUT_) {
        float s = 0.0f;
#pragma unroll
        for (int j = 0; j < 8; j++) s += red[t * 8 + j];
        out[b * OUT_ + t] = s;
    }
}

// ---------------------------------------------------------------------------
extern "C" void kernel_launch(void* const* d_in, const int* in_sizes, int n_in,
                              void* d_out, int out_size) {
    const float* x     = (const float*)d_in[0];
    const float* coef1 = (const float*)d_in[1];
    const float* sb1   = (const float*)d_in[2];
    const float* ssp1  = (const float*)d_in[3];
    const float* coef2 = (const float*)d_in[4];
    const float* sb2   = (const float*)d_in[5];
    const float* ssp2  = (const float*)d_in[6];
    float* out = (float*)d_out;

    cudaFuncSetAttribute(k2_mma, cudaFuncAttributeMaxDynamicSharedMemorySize, SMEM_TOTAL);
    k2_mma<<<dim3(2, KSPLIT), 512, SMEM_TOTAL>>>(x, coef1, sb1, ssp1);
    k3a_reduce<<<(B_ * H_) / (32 * 4), 256>>>();
    k3b_layer2<<<B_, 256>>>(coef2, sb2, ssp2, out);
}

// round 16
// speedup vs baseline: 1.4268x; 1.0265x over previous
#include <cuda_runtime.h>
#include <cuda_fp16.h>
#include <cstdint>

// ---------------------------------------------------------------------------
// KAN 2-layer fused, round 16: R15 design (16-input chunks, uniform 9 x K16
// mma steps, 2-stage ring, fused K3) + the missing consumer-wide barrier
// between the last stage-0 consume and the writeout scratch stores (R15's
// NaN was fast consumer warps overwriting stage 0 while slow warps still
// ldsm'd it — S overlaps stage 0 in the 2-stage layout).
//   512 threads: warps 0-7 consume (ldmatrix + m16n8k16), warps 8-15 produce.
//   Tile rows: fp16[128][152] (304B row; k = i*8+g basis, 128+i silu/sb).
//   K2 CTA: M=128 (o) x N=128 (b) x K=432; grid (2 o-tiles x 64 splits).
// ---------------------------------------------------------------------------

#define B_     128
#define IN_    3072
#define H_     256
#define OUT_   10
#define KSPLIT 64
#define IPC    48
#define NSUB   6            // producer sub-phases (8 inputs each)
#define ROWB   304          // bytes per tile row (76 words = 12 mod 32)
#define TILEB  (128 * ROWB) // 38912
#define STGB   (2 * TILEB)  // A tile + B tile = 77824
#define SMEM_TOTAL (2 * STGB)   // 155648
#define SP     132

__device__ __half g_Y1ph[KSPLIT * B_ * H_];   // layer-1 partials, fp16 (4MB)

// ---- helpers ---------------------------------------------------------------
__device__ __forceinline__ uint32_t smem_u32(const void* p) {
    uint32_t a;
    asm("{ .reg .u64 t; cvta.to.shared.u64 t, %1; cvt.u32.u64 %0, t; }" : "=r"(a) : "l"(p));
    return a;
}
__device__ __forceinline__ uint32_t packh2(float lo, float hi) {
    __half2 h = __floats2half2_rn(lo, hi);
    return *(uint32_t*)&h;
}
__device__ __forceinline__ uint16_t h16(float v) {
    __half h = __float2half_rn(v);
    return __half_as_ushort(h);
}
__device__ __forceinline__ uint4 ldsm_x4(uint32_t a) {
    uint4 r;
    asm volatile("ldmatrix.sync.aligned.m8n8.x4.shared.b16 {%0,%1,%2,%3}, [%4];"
        : "=r"(r.x), "=r"(r.y), "=r"(r.z), "=r"(r.w) : "r"(a));
    return r;
}
__device__ __forceinline__ uint2 ldsm_x2(uint32_t a) {
    uint2 r;
    asm volatile("ldmatrix.sync.aligned.m8n8.x2.shared.b16 {%0,%1}, [%2];"
        : "=r"(r.x), "=r"(r.y) : "r"(a));
    return r;
}
__device__ __forceinline__ void mma16(float d[4], const uint4& a, const uint2& b) {
    asm volatile("mma.sync.aligned.m16n8k16.row.col.f32.f16.f16.f32 "
        "{%0,%1,%2,%3}, {%4,%5,%6,%7}, {%8,%9}, {%0,%1,%2,%3};"
        : "+f"(d[0]), "+f"(d[1]), "+f"(d[2]), "+f"(d[3])
        : "r"(a.x), "r"(a.y), "r"(a.z), "r"(a.w), "r"(b.x), "r"(b.y));
}
#define BARS(id, cnt) asm volatile("bar.sync %0, %1;"   :: "r"(id), "r"(cnt) : "memory")
#define BARA(id, cnt) asm volatile("bar.arrive %0, %1;" :: "r"(id), "r"(cnt) : "memory")

__device__ __forceinline__ float silu_f(float x) { return x / (1.0f + __expf(-x)); }
__device__ __forceinline__ float selu_f(float x) {
    const float scale = 1.0507009873554805f;
    const float alpha = 1.6732632423543772f;
    return x > 0.0f ? scale * x : scale * alpha * expm1f(x);
}

// Closed-form cubic B-spline (validated rounds 4-14 vs Cox-de-Boor).
struct Bsp { float w0, w1, w2, w3; int m; };
__device__ __forceinline__ Bsp bspline4(float x) {
    Bsp r;
    float tpos = (x + 2.2f) * 2.5f;
    float mf = floorf(tpos);
    r.m = (int)mf;
    float u = tpos - mf;
    float u2 = u * u, u3 = u2 * u, om = 1.0f - u;
    bool valid = (x >= -2.2f) && (r.m <= 10);
    float s = valid ? (1.0f / 6.0f) : 0.0f;
    r.w0 = om * om * om * s;
    r.w1 = (3.0f * u3 - 6.0f * u2 + 4.0f) * s;
    r.w2 = (-3.0f * u3 + 3.0f * u2 + 3.0f * u + 1.0f) * s;
    r.w3 = u3 * s;
    return r;
}
__device__ __forceinline__ float bsp_at(const Bsp& r, int g) {
    int d = r.m - g;
    float v = 0.0f;
    v = (d == 3) ? r.w0 : v;
    v = (d == 2) ? r.w1 : v;
    v = (d == 1) ? r.w2 : v;
    v = (d == 0) ? r.w3 : v;
    return v;
}

// ---------------------------------------------------------------------------
// K2: warp-specialized layer-1 GEMM, 16-input chunks, 2-stage decoupled ring.
//   Full barriers 1,2 (producer arrives); free barriers 4,5 (consumer
//   arrives); barrier 7 = consumer-internal (drain + transpose handoff).
// ---------------------------------------------------------------------------
__global__ void __launch_bounds__(512, 1) k2_mma(const float* __restrict__ x,
                                                const float* __restrict__ coef1,
                                                const float* __restrict__ sb1,
                                                const float* __restrict__ ssp1) {
    extern __shared__ __align__(16) char smem[];

    const int tid  = threadIdx.x;
    const int o0   = blockIdx.x * 128;
    const int split = blockIdx.y;
    const int ibase0 = split * IPC;

    if (tid >= 256) {
        // =================== PRODUCER (warps 8-15) ===================
        const int ptid = tid - 256;

        float4 pc[8];
        float  psp[8], psb[4], px[4];

        auto ldgA = [&](int ib) {
#pragma unroll
            for (int k = 0; k < 8; k++) {           // coalesced
                int f = ptid + 256 * k;
                int o = f >> 4, i2 = (f >> 1) & 7, h = f & 1;
                int e = (o0 + o) * IN_ + ib + i2;
                pc[k]  = ((const float4*)coef1)[e * 2 + h];
                psp[k] = ssp1[e];
            }
#pragma unroll
            for (int k = 0; k < 4; k++) {
                int f = ptid + 256 * k;
                int o = f >> 3, i2 = f & 7;
                psb[k] = sb1[(o0 + o) * IN_ + ib + i2];
            }
        };
        auto ldgB = [&](int ib) {
#pragma unroll
            for (int u = 0; u < 4; u++) {
                int f = ptid + 256 * u;
                int b = f >> 3, i2 = f & 7;
                px[u] = x[b * IN_ + ib + i2];
            }
        };
        auto stsA = [&](char* As, int half) {
            const int i0g = half * 8;
#pragma unroll
            for (int k = 0; k < 8; k++) {
                int f = ptid + 256 * k;
                int o = f >> 4, i2 = (f >> 1) & 7, h = f & 1;
                uint2 v;
                v.x = packh2(psp[k] * pc[k].x, psp[k] * pc[k].y);
                v.y = packh2(psp[k] * pc[k].z, psp[k] * pc[k].w);
                *(uint2*)(As + o * ROWB + (i0g + i2) * 16 + h * 8) = v;
            }
#pragma unroll
            for (int k = 0; k < 4; k++) {
                int f = ptid + 256 * k;
                int o = f >> 3, i2 = f & 7;
                *(uint16_t*)(As + o * ROWB + 256 + (i0g + i2) * 2) = h16(psb[k]);
            }
        };
        auto prodB = [&](char* Bb, int half) {
            const int i0g = half * 8;
#pragma unroll
            for (int u = 0; u < 4; u++) {
                int f = ptid + 256 * u;
                int b = f >> 3, i2 = f & 7;
                char* row = Bb + b * ROWB;
                *(uint4*)(row + (i0g + i2) * 16) = make_uint4(0u, 0u, 0u, 0u);
                Bsp q = bspline4(px[u]);
                float w[4] = { q.w0, q.w1, q.w2, q.w3 };
#pragma unroll
                for (int kk = 0; kk < 4; kk++) {
                    int g = q.m - 3 + kk;
                    if (g >= 0 && g <= 7)
                        *(uint16_t*)(row + (i0g + i2) * 16 + g * 2) = h16(w[kk]);
                }
                *(uint16_t*)(row + 256 + (i0g + i2) * 2) = h16(silu_f(px[u]));
            }
        };

        ldgA(ibase0); ldgB(ibase0);
        for (int u = 0; u < NSUB; u++) {
            const int t = u >> 1, half = u & 1;
            if (!half && t >= 2) BARS(4 + (t & 1), 512);   // stage free?
            char* stg = smem + (t & 1) * STGB;
            stsA(stg, half);
            if (u + 1 < NSUB) ldgA(ibase0 + (u + 1) * 8);
            prodB(stg + TILEB, half);
            if (u + 1 < NSUB) ldgB(ibase0 + (u + 1) * 8);
            if (half) BARA(1 + (t & 1), 512);              // stage full
        }
        return;
    }

    // =================== CONSUMER (warps 0-7) ===================
    const int lane = tid & 31;
    const int wid  = tid >> 5;
    const int wm   = wid >> 2;          // 0..1 : 64 o per warp
    const int wn   = wid & 3;           // 0..3 : 32 b per warp

    float acc[4][4][4];
#pragma unroll
    for (int mi = 0; mi < 4; mi++)
#pragma unroll
        for (int ni = 0; ni < 4; ni++)
#pragma unroll
            for (int w = 0; w < 4; w++) acc[mi][ni][w] = 0.0f;

    const uint32_t sb32 = smem_u32(smem);
    const uint32_t laneA = ((lane & 7) + ((lane >> 3) & 1) * 8) * ROWB
                         + ((lane >> 4) & 1) * 16;
    const uint32_t laneB = (lane & 7) * ROWB + ((lane >> 3) & 1) * 16;
    uint32_t rowA[4], rowB[4];
#pragma unroll
    for (int mi = 0; mi < 4; mi++) rowA[mi] = (uint32_t)((wm * 4 + mi) * 16) * ROWB;
#pragma unroll
    for (int ni = 0; ni < 4; ni++) rowB[ni] = TILEB + (uint32_t)((wn * 4 + ni) * 8) * ROWB;

    for (int t = 0; t < 3; t++) {
        BARS(1 + (t & 1), 512);                 // stage t full
        const uint32_t stg = sb32 + (uint32_t)(t & 1) * STGB;
#pragma unroll
        for (int j = 0; j < 9; j++) {           // j=8 is the silu/sb K block
            uint4 af[4];
            uint2 bf[4];
#pragma unroll
            for (int mi = 0; mi < 4; mi++)
                af[mi] = ldsm_x4(stg + rowA[mi] + laneA + 32 * j);
#pragma unroll
            for (int ni = 0; ni < 4; ni++)
                bf[ni] = ldsm_x2(stg + rowB[ni] + laneB + 32 * j);
#pragma unroll
            for (int mi = 0; mi < 4; mi++)
#pragma unroll
                for (int ni = 0; ni < 4; ni++) mma16(acc[mi][ni], af[mi], bf[ni]);
        }
        if (t < 2) BARA(4 + (t & 1), 512);      // stage t free (producer reuse)
    }

    // --- writeout: DRAIN all consumer reads of stage 0 first (R15 bug fix),
    //     then transpose via smem, pack fp16, coalesced 8B stores ---
    {
        BARS(7, 256);                       // all consumers done reading smem
        float* S = (float*)smem;            // 128 x 132 floats = 67584 B
        const int r = lane >> 2, c = lane & 3;
#pragma unroll
        for (int mi = 0; mi < 4; mi++)
#pragma unroll
            for (int ni = 0; ni < 4; ni++)
#pragma unroll
                for (int w = 0; w < 4; w++) {
                    int o_l = (wm * 4 + mi) * 16 + r + 8 * (w >> 1);
                    int b_l = (wn * 4 + ni) * 8 + 2 * c + (w & 1);
                    S[b_l * SP + o_l] = acc[mi][ni][w];
                }
        BARS(7, 256);                       // stores visible before reads
        __half* Yh = g_Y1ph + split * (B_ * H_);
#pragma unroll
        for (int p = 0; p < 16; p++) {
            int idx = tid + 256 * p;
            int bb = idx >> 5, o4 = idx & 31;
            float4 v = *(float4*)&S[bb * SP + o4 * 4];
            uint2 u;
            u.x = packh2(v.x, v.y);
            u.y = packh2(v.z, v.w);
            *(uint2*)(Yh + bb * H_ + o0 + o4 * 4) = u;
        }
    }
}

// ---------------------------------------------------------------------------
// K3 (fused): split-reduce fp16 partials + selu + layer 2.
// Grid 128 (batch), block 256 (hidden unit).
// ---------------------------------------------------------------------------
__global__ void __launch_bounds__(256) k3_fused(const float* __restrict__ coef2,
                                               const float* __restrict__ sb2,
                                               const float* __restrict__ ssp2,
                                               float* __restrict__ out) {
    const int b = blockIdx.x;
    const int t = threadIdx.x;
    const int lane = t & 31, w = t >> 5;

    // split reduction: 64 coalesced half loads, fp32 accumulate
    const __half* P = g_Y1ph + b * H_ + t;
    float y = 0.0f;
#pragma unroll
    for (int s = 0; s < KSPLIT; s++)
        y += __half2float(P[(size_t)s * (B_ * H_)]);

    float h = selu_f(y);
    Bsp bs = bspline4(h);
    float f0 = silu_f(h);
    float fb[8];
#pragma unroll
    for (int g = 0; g < 8; g++) fb[g] = bsp_at(bs, g);

    __shared__ float red[OUT_ * 8];
    float val[OUT_];
#pragma unroll
    for (int o = 0; o < OUT_; o++) {
        int e = o * H_ + t;
        float4 c0 = ((const float4*)coef2)[e * 2];
        float4 c1 = ((const float4*)coef2)[e * 2 + 1];
        float sp = ssp2[e];
        float spline = fb[0] * c0.x + fb[1] * c0.y + fb[2] * c0.z + fb[3] * c0.w
                     + fb[4] * c1.x + fb[5] * c1.y + fb[6] * c1.z + fb[7] * c1.w;
        val[o] = sb2[e] * f0 + sp * spline;
    }
#pragma unroll
    for (int o = 0; o < OUT_; o++) {
#pragma unroll
        for (int off = 16; off > 0; off >>= 1)
            val[o] += __shfl_down_sync(0xFFFFFFFFu, val[o], off);
    }
    if (lane == 0) {
#pragma unroll
        for (int o = 0; o < OUT_; o++) red[o * 8 + w] = val[o];
    }
    __syncthreads();
    if (t < OUT_) {
        float s = 0.0f;
#pragma unroll
        for (int j = 0; j < 8; j++) s += red[t * 8 + j];
        out[b * OUT_ + t] = s;
    }
}

// ---------------------------------------------------------------------------
extern "C" void kernel_launch(void* const* d_in, const int* in_sizes, int n_in,
                              void* d_out, int out_size) {
    const float* x     = (const float*)d_in[0];
    const float* coef1 = (const float*)d_in[1];
    const float* sb1   = (const float*)d_in[2];
    const float* ssp1  = (const float*)d_in[3];
    const float* coef2 = (const float*)d_in[4];
    const float* sb2   = (const float*)d_in[5];
    const float* ssp2  = (const float*)d_in[6];
    float* out = (float*)d_out;

    cudaFuncSetAttribute(k2_mma, cudaFuncAttributeMaxDynamicSharedMemorySize, SMEM_TOTAL);
    k2_mma<<<dim3(2, KSPLIT), 512, SMEM_TOTAL>>>(x, coef1, sb1, ssp1);
    k3_fused<<<B_, 256>>>(coef2, sb2, ssp2, out);
}